// round 1
// baseline (speedup 1.0000x reference)
#include <cuda_runtime.h>
#include <cstdint>
#include <math.h>

// Problem dims (fixed)
#define NN 16
#define CC 256
#define OO 256
#define HH 64
#define WW 64
#define HWP (HH * WW)     // 4096 pixels per image

// Scratch (device globals: allocation-free per harness rules)
__device__ float g_xT[(size_t)NN * HWP * CC];  // NHWC transposed input, 67 MB
__device__ float g_wT[9 * CC * OO];            // [tap][c][o], 2.36 MB

// ---------------------------------------------------------------------------
// Kernel 1: NCHW -> NHWC transpose of x (per image: 256 x 4096 -> 4096 x 256)
// ---------------------------------------------------------------------------
__global__ void transpose_x_kernel(const float* __restrict__ x) {
    __shared__ float tile[32][33];
    const int n  = blockIdx.z;
    const int s0 = blockIdx.x * 32;   // spatial (h*W+w)
    const int c0 = blockIdx.y * 32;   // channel
    const int tx = threadIdx.x, ty = threadIdx.y;

    const float* xp = x + (size_t)n * CC * HWP;
#pragma unroll
    for (int j = 0; j < 4; j++) {
        tile[ty + j * 8][tx] = xp[(size_t)(c0 + ty + j * 8) * HWP + s0 + tx];
    }
    __syncthreads();
    float* xt = g_xT + (size_t)n * HWP * CC;
#pragma unroll
    for (int j = 0; j < 4; j++) {
        xt[(size_t)(s0 + ty + j * 8) * CC + c0 + tx] = tile[tx][ty + j * 8];
    }
}

// ---------------------------------------------------------------------------
// Kernel 2: w_def (O,C,3,3) -> g_wT[k][c][o]
// ---------------------------------------------------------------------------
__global__ void transpose_w_kernel(const float* __restrict__ w_def) {
    int idx = blockIdx.x * blockDim.x + threadIdx.x;
    if (idx >= 9 * CC * OO) return;
    int k = idx / (CC * OO);
    int r = idx - k * (CC * OO);
    int c = r >> 8;     // / OO
    int o = r & 255;    // % OO
    g_wT[idx] = w_def[((size_t)o * CC + c) * 9 + k];
}

// ---------------------------------------------------------------------------
// Kernel 3: fused deform-sample + GEMM + ReLU + w_cls reduction.
// One block per (image, row): 64 pixels. 256 threads.
//   GEMM mapping: thread t -> og = t/8 (8 outputs o), pg = t%8 (8 pixels p);
//                 acc[8][8] fp32 registers, K accumulated over 9 taps x 256 c.
//   Sampling mapping: thread t -> pixel sp = t/4, channel quarter scq = t%4.
// Smem: sS[256][SMP] sampled tile, wS[64][SMW] weight chunk.
// ---------------------------------------------------------------------------
#define SMP 68     // sS row stride (floats): 64 px + pad, keeps 16B alignment
#define SMW 264    // wS row stride (floats): 256 o + pad, 16B-aligned
#define SMEM_BYTES (256 * SMP * 4 + 64 * SMW * 4)   // 69632 + 67584 = 137216

__global__ void __launch_bounds__(256)
deform_main_kernel(const float* __restrict__ off,
                   const float* __restrict__ wcls,
                   const float* __restrict__ bcls,
                   float* __restrict__ out) {
    extern __shared__ float sm[];
    float* sS = sm;                 // [256][SMP]
    float* wS = sm + 256 * SMP;     // [64][SMW]

    const int blk = blockIdx.x;
    const int n = blk >> 6;         // image
    const int h = blk & 63;         // row
    const int t = threadIdx.x;

    // GEMM thread mapping
    const int og = t >> 3, pg = t & 7;
    const int o0 = og << 3, p0 = pg << 3;

    // Sampling thread mapping
    const int sp = t >> 2;          // pixel (0..63)
    const int scq = t & 3;          // channel quarter (64 ch each)

    float acc[8][8];
#pragma unroll
    for (int i = 0; i < 8; i++)
#pragma unroll
        for (int j = 0; j < 8; j++) acc[i][j] = 0.f;

    const float* offpix = off + (size_t)(n * HWP + h * WW + sp) * 18;
    const float* xbase = g_xT + (size_t)n * HWP * CC;

#pragma unroll 1
    for (int k = 0; k < 9; k++) {
        // ---------------- phase 1: bilinear sample tap k into sS ----------------
        const float dy = offpix[2 * k];
        const float dx = offpix[2 * k + 1];
        const float py = (float)(h + (k / 3) - 1) + dy;
        const float px = (float)(sp + (k % 3) - 1) + dx;
        const float y0f = floorf(py), x0f = floorf(px);
        const float fy = py - y0f, fx = px - x0f;
        const int y0 = (int)y0f, x0 = (int)x0f;
        const int y1 = y0 + 1, x1 = x0 + 1;
        float w00 = (1.f - fy) * (1.f - fx);
        float w01 = (1.f - fy) * fx;
        float w10 = fy * (1.f - fx);
        float w11 = fy * fx;
        const bool vy0 = ((unsigned)y0 < (unsigned)HH);
        const bool vy1 = ((unsigned)y1 < (unsigned)HH);
        const bool vx0 = ((unsigned)x0 < (unsigned)WW);
        const bool vx1 = ((unsigned)x1 < (unsigned)WW);
        if (!(vy0 && vx0)) w00 = 0.f;
        if (!(vy0 && vx1)) w01 = 0.f;
        if (!(vy1 && vx0)) w10 = 0.f;
        if (!(vy1 && vx1)) w11 = 0.f;
        const int yc0 = min(max(y0, 0), HH - 1);
        const int yc1 = min(max(y1, 0), HH - 1);
        const int xc0 = min(max(x0, 0), WW - 1);
        const int xc1 = min(max(x1, 0), WW - 1);

        const float4* A = (const float4*)(xbase + ((yc0 * WW + xc0) * CC + (scq << 6)));
        const float4* B = (const float4*)(xbase + ((yc0 * WW + xc1) * CC + (scq << 6)));
        const float4* Cq = (const float4*)(xbase + ((yc1 * WW + xc0) * CC + (scq << 6)));
        const float4* D = (const float4*)(xbase + ((yc1 * WW + xc1) * CC + (scq << 6)));

        __syncthreads();   // previous tap's GEMM done reading sS
#pragma unroll
        for (int i = 0; i < 16; i++) {
            const float4 a = A[i], b4 = B[i], c4 = Cq[i], d4 = D[i];
            const int cb = (scq << 6) + (i << 2);
            sS[(cb + 0) * SMP + sp] = w00 * a.x + w01 * b4.x + w10 * c4.x + w11 * d4.x;
            sS[(cb + 1) * SMP + sp] = w00 * a.y + w01 * b4.y + w10 * c4.y + w11 * d4.y;
            sS[(cb + 2) * SMP + sp] = w00 * a.z + w01 * b4.z + w10 * c4.z + w11 * d4.z;
            sS[(cb + 3) * SMP + sp] = w00 * a.w + w01 * b4.w + w10 * c4.w + w11 * d4.w;
        }

        // ---------------- phase 2: GEMM, K = 256 in 4 chunks of 64 ----------------
        const float* wk = g_wT + (size_t)k * (CC * OO);
#pragma unroll 1
        for (int ch = 0; ch < 4; ch++) {
            __syncthreads();   // sS ready (ch==0) / previous wS consumed (ch>0)
            // stage 64x256 weight chunk (contiguous in global) into wS
            const float4* src = (const float4*)(wk + ch * 64 * 256);
#pragma unroll
            for (int i = 0; i < 16; i++) {
                const int idx = t + (i << 8);        // 0..4095 float4s
                const int r = idx >> 6;              // row (c within chunk)
                const int col = (idx & 63) << 2;     // o
                *(float4*)(wS + r * SMW + col) = src[idx];
            }
            __syncthreads();
#pragma unroll 2
            for (int cc = 0; cc < 64; cc++) {
                const float* srow = sS + ((ch << 6) + cc) * SMP + p0;
                const float4 s0 = *(const float4*)srow;
                const float4 s1 = *(const float4*)(srow + 4);
                const float* wrow = wS + cc * SMW + o0;
                const float4 w0 = *(const float4*)wrow;
                const float4 w1 = *(const float4*)(wrow + 4);
                const float sv[8] = {s0.x, s0.y, s0.z, s0.w, s1.x, s1.y, s1.z, s1.w};
                const float wv[8] = {w0.x, w0.y, w0.z, w0.w, w1.x, w1.y, w1.z, w1.w};
#pragma unroll
                for (int oi = 0; oi < 8; oi++)
#pragma unroll
                    for (int pi = 0; pi < 8; pi++)
                        acc[oi][pi] = fmaf(wv[oi], sv[pi], acc[oi][pi]);
            }
        }
    }

    // ---------------- epilogue: ReLU + w_cls dot + cross-og reduction ----------------
    float part[8];
#pragma unroll
    for (int pi = 0; pi < 8; pi++) part[pi] = 0.f;
#pragma unroll
    for (int oi = 0; oi < 8; oi++) {
        const float wc = wcls[o0 + oi];
#pragma unroll
        for (int pi = 0; pi < 8; pi++)
            part[pi] = fmaf(wc, fmaxf(acc[oi][pi], 0.f), part[pi]);
    }
    __syncthreads();   // done with sS as sample buffer
#pragma unroll
    for (int pi = 0; pi < 8; pi++)
        sS[og * 64 + p0 + pi] = part[pi];
    __syncthreads();
    if (t < 64) {
        float v = bcls[0];
#pragma unroll
        for (int g = 0; g < 32; g++) v += sS[g * 64 + t];
        out[(size_t)n * HWP + h * WW + t] = v;
    }
}

// ---------------------------------------------------------------------------
// Launch
// ---------------------------------------------------------------------------
extern "C" void kernel_launch(void* const* d_in, const int* in_sizes, int n_in,
                              void* d_out, int out_size) {
    const float* x      = (const float*)d_in[0];
    const float* offset = (const float*)d_in[1];
    const float* w_def  = (const float*)d_in[2];
    const float* w_cls  = (const float*)d_in[3];
    const float* b_cls  = (const float*)d_in[4];
    float* out = (float*)d_out;

    // 1. x: NCHW -> NHWC
    dim3 g1(HWP / 32, CC / 32, NN), b1(32, 8);
    transpose_x_kernel<<<g1, b1>>>(x);

    // 2. w_def -> [tap][c][o]
    transpose_w_kernel<<<(9 * CC * OO + 255) / 256, 256>>>(w_def);

    // 3. fused deform conv + relu + cls
    cudaFuncSetAttribute(deform_main_kernel,
                         cudaFuncAttributeMaxDynamicSharedMemorySize, SMEM_BYTES);
    deform_main_kernel<<<NN * HH, 256, SMEM_BYTES>>>(offset, w_cls, b_cls, out);
}

// round 2
// speedup vs baseline: 1.0002x; 1.0002x over previous
#include <cuda_runtime.h>
#include <cstdint>
#include <math.h>

// Problem dims (fixed)
#define NN 16
#define CC 256
#define OO 256
#define HH 64
#define WW 64
#define HWP (HH * WW)     // 4096 pixels per image

// Scratch (device globals: allocation-free per harness rules)
__device__ float g_xT[(size_t)NN * HWP * CC];  // NHWC transposed input, 67 MB
__device__ float g_wT[9 * CC * OO];            // [tap][c][o], 2.36 MB

// ---------------------------------------------------------------------------
// Kernel 1: NCHW -> NHWC transpose of x (per image: 256 x 4096 -> 4096 x 256)
// ---------------------------------------------------------------------------
__global__ void transpose_x_kernel(const float* __restrict__ x) {
    __shared__ float tile[32][33];
    const int n  = blockIdx.z;
    const int s0 = blockIdx.x * 32;   // spatial (h*W+w)
    const int c0 = blockIdx.y * 32;   // channel
    const int tx = threadIdx.x, ty = threadIdx.y;

    const float* xp = x + (size_t)n * CC * HWP;
#pragma unroll
    for (int j = 0; j < 4; j++) {
        tile[ty + j * 8][tx] = xp[(size_t)(c0 + ty + j * 8) * HWP + s0 + tx];
    }
    __syncthreads();
    float* xt = g_xT + (size_t)n * HWP * CC;
#pragma unroll
    for (int j = 0; j < 4; j++) {
        xt[(size_t)(s0 + ty + j * 8) * CC + c0 + tx] = tile[tx][ty + j * 8];
    }
}

// ---------------------------------------------------------------------------
// Kernel 2: w_def (O,C,3,3) -> g_wT[k][c][o]
// ---------------------------------------------------------------------------
__global__ void transpose_w_kernel(const float* __restrict__ w_def) {
    int idx = blockIdx.x * blockDim.x + threadIdx.x;
    if (idx >= 9 * CC * OO) return;
    int k = idx / (CC * OO);
    int r = idx - k * (CC * OO);
    int c = r >> 8;     // / OO
    int o = r & 255;    // % OO
    g_wT[idx] = w_def[((size_t)o * CC + c) * 9 + k];
}

// ---------------------------------------------------------------------------
// Kernel 3: fused deform-sample + GEMM + ReLU + w_cls reduction.
// One block per (image, row): 64 pixels. 256 threads.
//   GEMM mapping: thread t -> og = t/8 (8 outputs o), pg = t%8 (8 pixels p);
//                 acc[8][8] fp32 registers, K accumulated over 9 taps x 256 c.
//   Sampling mapping: thread t -> pixel sp = t/4, channel quarter scq = t%4.
// Smem: sS[256][SMP] sampled tile, wS[64][SMW] weight chunk.
// ---------------------------------------------------------------------------
#define SMP 68     // sS row stride (floats): 64 px + pad, keeps 16B alignment
#define SMW 264    // wS row stride (floats): 256 o + pad, 16B-aligned
#define SMEM_BYTES (256 * SMP * 4 + 64 * SMW * 4)   // 69632 + 67584 = 137216

__global__ void __launch_bounds__(256)
deform_main_kernel(const float* __restrict__ off,
                   const float* __restrict__ wcls,
                   const float* __restrict__ bcls,
                   float* __restrict__ out) {
    extern __shared__ float sm[];
    float* sS = sm;                 // [256][SMP]
    float* wS = sm + 256 * SMP;     // [64][SMW]

    const int blk = blockIdx.x;
    const int n = blk >> 6;         // image
    const int h = blk & 63;         // row
    const int t = threadIdx.x;

    // GEMM thread mapping
    const int og = t >> 3, pg = t & 7;
    const int o0 = og << 3, p0 = pg << 3;

    // Sampling thread mapping
    const int sp = t >> 2;          // pixel (0..63)
    const int scq = t & 3;          // channel quarter (64 ch each)

    float acc[8][8];
#pragma unroll
    for (int i = 0; i < 8; i++)
#pragma unroll
        for (int j = 0; j < 8; j++) acc[i][j] = 0.f;

    const float* offpix = off + (size_t)(n * HWP + h * WW + sp) * 18;
    const float* xbase = g_xT + (size_t)n * HWP * CC;

#pragma unroll 1
    for (int k = 0; k < 9; k++) {
        // ---------------- phase 1: bilinear sample tap k into sS ----------------
        const float dy = offpix[2 * k];
        const float dx = offpix[2 * k + 1];
        const float py = (float)(h + (k / 3) - 1) + dy;
        const float px = (float)(sp + (k % 3) - 1) + dx;
        const float y0f = floorf(py), x0f = floorf(px);
        const float fy = py - y0f, fx = px - x0f;
        const int y0 = (int)y0f, x0 = (int)x0f;
        const int y1 = y0 + 1, x1 = x0 + 1;
        float w00 = (1.f - fy) * (1.f - fx);
        float w01 = (1.f - fy) * fx;
        float w10 = fy * (1.f - fx);
        float w11 = fy * fx;
        const bool vy0 = ((unsigned)y0 < (unsigned)HH);
        const bool vy1 = ((unsigned)y1 < (unsigned)HH);
        const bool vx0 = ((unsigned)x0 < (unsigned)WW);
        const bool vx1 = ((unsigned)x1 < (unsigned)WW);
        if (!(vy0 && vx0)) w00 = 0.f;
        if (!(vy0 && vx1)) w01 = 0.f;
        if (!(vy1 && vx0)) w10 = 0.f;
        if (!(vy1 && vx1)) w11 = 0.f;
        const int yc0 = min(max(y0, 0), HH - 1);
        const int yc1 = min(max(y1, 0), HH - 1);
        const int xc0 = min(max(x0, 0), WW - 1);
        const int xc1 = min(max(x1, 0), WW - 1);

        const float4* A = (const float4*)(xbase + ((yc0 * WW + xc0) * CC + (scq << 6)));
        const float4* B = (const float4*)(xbase + ((yc0 * WW + xc1) * CC + (scq << 6)));
        const float4* Cq = (const float4*)(xbase + ((yc1 * WW + xc0) * CC + (scq << 6)));
        const float4* D = (const float4*)(xbase + ((yc1 * WW + xc1) * CC + (scq << 6)));

        __syncthreads();   // previous tap's GEMM done reading sS
#pragma unroll
        for (int i = 0; i < 16; i++) {
            const float4 a = A[i], b4 = B[i], c4 = Cq[i], d4 = D[i];
            const int cb = (scq << 6) + (i << 2);
            sS[(cb + 0) * SMP + sp] = w00 * a.x + w01 * b4.x + w10 * c4.x + w11 * d4.x;
            sS[(cb + 1) * SMP + sp] = w00 * a.y + w01 * b4.y + w10 * c4.y + w11 * d4.y;
            sS[(cb + 2) * SMP + sp] = w00 * a.z + w01 * b4.z + w10 * c4.z + w11 * d4.z;
            sS[(cb + 3) * SMP + sp] = w00 * a.w + w01 * b4.w + w10 * c4.w + w11 * d4.w;
        }

        // ---------------- phase 2: GEMM, K = 256 in 4 chunks of 64 ----------------
        const float* wk = g_wT + (size_t)k * (CC * OO);
#pragma unroll 1
        for (int ch = 0; ch < 4; ch++) {
            __syncthreads();   // sS ready (ch==0) / previous wS consumed (ch>0)
            // stage 64x256 weight chunk (contiguous in global) into wS
            const float4* src = (const float4*)(wk + ch * 64 * 256);
#pragma unroll
            for (int i = 0; i < 16; i++) {
                const int idx = t + (i << 8);        // 0..4095 float4s
                const int r = idx >> 6;              // row (c within chunk)
                const int col = (idx & 63) << 2;     // o
                *(float4*)(wS + r * SMW + col) = src[idx];
            }
            __syncthreads();
#pragma unroll 2
            for (int cc = 0; cc < 64; cc++) {
                const float* srow = sS + ((ch << 6) + cc) * SMP + p0;
                const float4 s0 = *(const float4*)srow;
                const float4 s1 = *(const float4*)(srow + 4);
                const float* wrow = wS + cc * SMW + o0;
                const float4 w0 = *(const float4*)wrow;
                const float4 w1 = *(const float4*)(wrow + 4);
                const float sv[8] = {s0.x, s0.y, s0.z, s0.w, s1.x, s1.y, s1.z, s1.w};
                const float wv[8] = {w0.x, w0.y, w0.z, w0.w, w1.x, w1.y, w1.z, w1.w};
#pragma unroll
                for (int oi = 0; oi < 8; oi++)
#pragma unroll
                    for (int pi = 0; pi < 8; pi++)
                        acc[oi][pi] = fmaf(wv[oi], sv[pi], acc[oi][pi]);
            }
        }
    }

    // ---------------- epilogue: ReLU + w_cls dot + cross-og reduction ----------------
    float part[8];
#pragma unroll
    for (int pi = 0; pi < 8; pi++) part[pi] = 0.f;
#pragma unroll
    for (int oi = 0; oi < 8; oi++) {
        const float wc = wcls[o0 + oi];
#pragma unroll
        for (int pi = 0; pi < 8; pi++)
            part[pi] = fmaf(wc, fmaxf(acc[oi][pi], 0.f), part[pi]);
    }
    __syncthreads();   // done with sS as sample buffer
#pragma unroll
    for (int pi = 0; pi < 8; pi++)
        sS[og * 64 + p0 + pi] = part[pi];
    __syncthreads();
    if (t < 64) {
        float v = bcls[0];
#pragma unroll
        for (int g = 0; g < 32; g++) v += sS[g * 64 + t];
        out[(size_t)n * HWP + h * WW + t] = v;
    }
}

// ---------------------------------------------------------------------------
// Launch
// ---------------------------------------------------------------------------
extern "C" void kernel_launch(void* const* d_in, const int* in_sizes, int n_in,
                              void* d_out, int out_size) {
    const float* x      = (const float*)d_in[0];
    const float* offset = (const float*)d_in[1];
    const float* w_def  = (const float*)d_in[2];
    const float* w_cls  = (const float*)d_in[3];
    const float* b_cls  = (const float*)d_in[4];
    float* out = (float*)d_out;

    // 1. x: NCHW -> NHWC
    dim3 g1(HWP / 32, CC / 32, NN), b1(32, 8);
    transpose_x_kernel<<<g1, b1>>>(x);

    // 2. w_def -> [tap][c][o]
    transpose_w_kernel<<<(9 * CC * OO + 255) / 256, 256>>>(w_def);

    // 3. fused deform conv + relu + cls
    cudaFuncSetAttribute(deform_main_kernel,
                         cudaFuncAttributeMaxDynamicSharedMemorySize, SMEM_BYTES);
    deform_main_kernel<<<NN * HH, 256, SMEM_BYTES>>>(offset, w_cls, b_cls, out);
}

// round 4
// speedup vs baseline: 1.9938x; 1.9933x over previous
#include <cuda_runtime.h>
#include <cuda_bf16.h>
#include <cstdint>
#include <math.h>

#define NN 16
#define CC 256
#define OO 256
#define HWP 4096
#define NCHUNK 72          // 9 taps x 8 chunks of 32 channels

__device__ float g_xT[(size_t)NN * HWP * CC];        // NHWC f32 input
__device__ float g_wBp[(size_t)NCHUNK * 8704];       // per chunk: Bh[256o][17w], Bl at +4352 (bf16x2 packed)

// ---------------- helpers ----------------
__device__ __forceinline__ uint32_t pack_bf16x2(float lo, float hi) {
    __nv_bfloat162 t = __floats2bfloat162_rn(lo, hi);   // .x = lo (low 16 bits)
    return *(uint32_t*)&t;
}
__device__ __forceinline__ void mma16816(float* c, uint32_t a0, uint32_t a1,
                                         uint32_t a2, uint32_t a3,
                                         uint32_t b0, uint32_t b1) {
    asm volatile(
        "mma.sync.aligned.m16n8k16.row.col.f32.bf16.bf16.f32 "
        "{%0,%1,%2,%3}, {%4,%5,%6,%7}, {%8,%9}, {%0,%1,%2,%3};"
        : "+f"(c[0]), "+f"(c[1]), "+f"(c[2]), "+f"(c[3])
        : "r"(a0), "r"(a1), "r"(a2), "r"(a3), "r"(b0), "r"(b1));
}

// ---------------- kernel 1: NCHW -> NHWC ----------------
__global__ void transpose_x_kernel(const float* __restrict__ x) {
    __shared__ float tile[32][33];
    const int n = blockIdx.z, s0 = blockIdx.x * 32, c0 = blockIdx.y * 32;
    const int tx = threadIdx.x, ty = threadIdx.y;
    const float* xp = x + (size_t)n * CC * HWP;
#pragma unroll
    for (int j = 0; j < 4; j++)
        tile[ty + j * 8][tx] = xp[(size_t)(c0 + ty + j * 8) * HWP + s0 + tx];
    __syncthreads();
    float* xt = g_xT + (size_t)n * HWP * CC;
#pragma unroll
    for (int j = 0; j < 4; j++)
        xt[(size_t)(s0 + ty + j * 8) * CC + c0 + tx] = tile[tx][ty + j * 8];
}

// ---------------- kernel 2: weight bf16 hi/lo split, stride-17 pair layout ----------------
// g_wBp[chunk*8704 + o*17 + p] = pack(hi(w[c=2p]), hi(w[c=2p+1])); +4352 for lo residuals.
__global__ void wprep_kernel(const float* __restrict__ wdef) {
    int idx = blockIdx.x * blockDim.x + threadIdx.x;
    if (idx >= NCHUNK * 256 * 16) return;
    int p = idx & 15, o = (idx >> 4) & 255, chunk = idx >> 12;
    int tap = chunk >> 3, cgrp = chunk & 7;
    int c0 = cgrp * 32 + 2 * p;
    float w0 = wdef[((size_t)o * CC + c0) * 9 + tap];
    float w1 = wdef[((size_t)o * CC + c0 + 1) * 9 + tap];
    __nv_bfloat16 h0 = __float2bfloat16_rn(w0), h1 = __float2bfloat16_rn(w1);
    float l0 = w0 - __bfloat162float(h0), l1 = w1 - __bfloat162float(h1);
    float* dst = g_wBp + (size_t)chunk * 8704;
    __nv_bfloat162 hp; hp.x = h0; hp.y = h1;
    dst[o * 17 + p] = __uint_as_float(*(uint32_t*)&hp);
    dst[4352 + o * 17 + p] = __uint_as_float(pack_bf16x2(l0, l1));
}

// ---------------- kernel 3: fused deform + mma.sync GEMM + relu + cls ----------------
// SMEM word offsets
#define W_COORD 0            // [128 px][8]: o00,o01,o10,o11 (int bits), w00,w01,w10,w11
#define W_RED   1024         // [4 ng][128 px]
#define W_A     1536         // Ah [16 p][133], Al at +2128
#define W_AL    (W_A + 2128)
#define W_B     5792         // Bh [256 o][17], Bl at +4352
#define W_BL    (W_B + 4352)
#define SMEM_WORDS 14496
#define SMEM_BYTES (SMEM_WORDS * 4)   // 57984

__global__ void __launch_bounds__(256, 1)
deform_mma_kernel(const float* __restrict__ off, const float* __restrict__ wcls,
                  const float* __restrict__ bcls, float* __restrict__ out) {
    extern __shared__ float sm[];
    int* smi = (int*)sm;
    const int t = threadIdx.x, lane = t & 31, w = t >> 5;
    const int mg = w >> 2, ng = w & 3;               // warp tile: px[mg*64..], o[ng*64..]
    const int n = blockIdx.x >> 5, pblk = blockIdx.x & 31;
    const int px0 = pblk * 128;
    const float* xb = g_xT + (size_t)n * HWP * CC;

    float acc[4][8][4];
#pragma unroll
    for (int a = 0; a < 4; a++)
#pragma unroll
        for (int b = 0; b < 8; b++)
#pragma unroll
            for (int c = 0; c < 4; c++) acc[a][b][c] = 0.f;

#pragma unroll 1
    for (int chunk = 0; chunk < NCHUNK; ++chunk) {
        const int tap = chunk >> 3, cgrp = chunk & 7;
        if (chunk) __syncthreads();    // prev mma done reading A/B

        // ---- stage weights (2176 float4) ----
        {
            const float4* src = (const float4*)(g_wBp + (size_t)chunk * 8704);
            float4* dst = (float4*)(sm + W_B);
#pragma unroll
            for (int i = 0; i < 9; i++) {
                int idx = t + (i << 8);
                if (idx < 2176) dst[idx] = src[idx];
            }
        }
        // ---- per-tap coords (128 threads, once per 8 chunks) ----
        if (cgrp == 0 && t < 128) {
            const int gpix = px0 + t, h = gpix >> 6, wx = gpix & 63;
            const float* op = off + (size_t)(n * HWP + gpix) * 18 + 2 * tap;
            const float dy = op[0], dx = op[1];
            const float py = (float)(h + tap / 3 - 1) + dy;
            const float pxx = (float)(wx + tap % 3 - 1) + dx;
            const float y0f = floorf(py), x0f = floorf(pxx);
            const float fy = py - y0f, fx = pxx - x0f;
            const int y0 = (int)y0f, x0 = (int)x0f, y1 = y0 + 1, x1 = x0 + 1;
            float w00 = (1.f - fy) * (1.f - fx), w01 = (1.f - fy) * fx;
            float w10 = fy * (1.f - fx), w11 = fy * fx;
            if (!((unsigned)y0 < 64u && (unsigned)x0 < 64u)) w00 = 0.f;
            if (!((unsigned)y0 < 64u && (unsigned)x1 < 64u)) w01 = 0.f;
            if (!((unsigned)y1 < 64u && (unsigned)x0 < 64u)) w10 = 0.f;
            if (!((unsigned)y1 < 64u && (unsigned)x1 < 64u)) w11 = 0.f;
            const int yc0 = min(max(y0, 0), 63), yc1 = min(max(y1, 0), 63);
            const int xc0 = min(max(x0, 0), 63), xc1 = min(max(x1, 0), 63);
            smi[W_COORD + t * 8 + 0] = (yc0 * 64 + xc0) * 256;
            smi[W_COORD + t * 8 + 1] = (yc0 * 64 + xc1) * 256;
            smi[W_COORD + t * 8 + 2] = (yc1 * 64 + xc0) * 256;
            smi[W_COORD + t * 8 + 3] = (yc1 * 64 + xc1) * 256;
            sm[W_COORD + t * 8 + 4] = w00; sm[W_COORD + t * 8 + 5] = w01;
            sm[W_COORD + t * 8 + 6] = w10; sm[W_COORD + t * 8 + 7] = w11;
        }
        __syncthreads();

        // ---- sample: thread covers 4 px (4g..4g+3) x 4 ch (float4 slot l8) ----
        {
            const int l8 = t & 7, g = t >> 3;
            const int cb = cgrp * 32 + l8 * 4;
            const int p = 2 * l8;
#pragma unroll
            for (int j = 0; j < 4; j++) {
                const int px = g * 4 + j;
                const int* ci = smi + W_COORD + px * 8;
                const float* cf = sm + W_COORD + px * 8;
                const float w00 = cf[4], w01 = cf[5], w10 = cf[6], w11 = cf[7];
                const float4 a = *(const float4*)(xb + ci[0] + cb);
                const float4 b = *(const float4*)(xb + ci[1] + cb);
                const float4 c = *(const float4*)(xb + ci[2] + cb);
                const float4 d = *(const float4*)(xb + ci[3] + cb);
                float v0 = w00 * a.x + w01 * b.x + w10 * c.x + w11 * d.x;
                float v1 = w00 * a.y + w01 * b.y + w10 * c.y + w11 * d.y;
                float v2 = w00 * a.z + w01 * b.z + w10 * c.z + w11 * d.z;
                float v3 = w00 * a.w + w01 * b.w + w10 * c.w + w11 * d.w;
                __nv_bfloat162 h01 = __floats2bfloat162_rn(v0, v1);
                __nv_bfloat162 h23 = __floats2bfloat162_rn(v2, v3);
                float l0 = v0 - __bfloat162float(h01.x);
                float l1 = v1 - __bfloat162float(h01.y);
                float l2 = v2 - __bfloat162float(h23.x);
                float l3 = v3 - __bfloat162float(h23.y);
                sm[W_A + p * 133 + px]        = __uint_as_float(*(uint32_t*)&h01);
                sm[W_A + (p + 1) * 133 + px]  = __uint_as_float(*(uint32_t*)&h23);
                sm[W_AL + p * 133 + px]       = __uint_as_float(pack_bf16x2(l0, l1));
                sm[W_AL + (p + 1) * 133 + px] = __uint_as_float(pack_bf16x2(l2, l3));
            }
        }
        __syncthreads();

        // ---- GEMM: 2 ktiles x 8 ntiles x 4 mtiles x 3 products ----
        const uint32_t* Ah = (const uint32_t*)(sm + W_A);
        const uint32_t* Al = (const uint32_t*)(sm + W_AL);
        const uint32_t* Bh = (const uint32_t*)(sm + W_B);
        const uint32_t* Bl = (const uint32_t*)(sm + W_BL);
        const int la = lane & 3, r = lane >> 2;
#pragma unroll
        for (int kt = 0; kt < 2; kt++) {
            uint32_t afh[4][4], afl[4][4];
            const int pa = kt * 8 + la;
#pragma unroll
            for (int mt = 0; mt < 4; mt++) {
                const int base = pa * 133 + mg * 64 + mt * 16 + r;
                afh[mt][0] = Ah[base];           afh[mt][1] = Ah[base + 8];
                afh[mt][2] = Ah[base + 4 * 133]; afh[mt][3] = Ah[base + 4 * 133 + 8];
                afl[mt][0] = Al[base];           afl[mt][1] = Al[base + 8];
                afl[mt][2] = Al[base + 4 * 133]; afl[mt][3] = Al[base + 4 * 133 + 8];
            }
#pragma unroll
            for (int nt = 0; nt < 8; nt++) {
                const int ob = (ng * 64 + nt * 8 + r) * 17 + kt * 8 + la;
                const uint32_t bh0 = Bh[ob], bh1 = Bh[ob + 4];
                const uint32_t bl0 = Bl[ob], bl1 = Bl[ob + 4];
#pragma unroll
                for (int mt = 0; mt < 4; mt++) {
                    mma16816(acc[mt][nt], afh[mt][0], afh[mt][1], afh[mt][2], afh[mt][3], bh0, bh1);
                    mma16816(acc[mt][nt], afh[mt][0], afh[mt][1], afh[mt][2], afh[mt][3], bl0, bl1);
                    mma16816(acc[mt][nt], afl[mt][0], afl[mt][1], afl[mt][2], afl[mt][3], bh0, bh1);
                }
            }
        }
    }

    // ---- epilogue: relu + wcls dot, reduce over o ----
    {
        const int la = lane & 3, r = lane >> 2;
        float s[4][2];
#pragma unroll
        for (int mt = 0; mt < 4; mt++) { s[mt][0] = 0.f; s[mt][1] = 0.f; }
#pragma unroll
        for (int nt = 0; nt < 8; nt++) {
            const int col = ng * 64 + nt * 8 + 2 * la;
            const float wc0 = __ldg(&wcls[col]), wc1 = __ldg(&wcls[col + 1]);
#pragma unroll
            for (int mt = 0; mt < 4; mt++) {
                s[mt][0] += wc0 * fmaxf(acc[mt][nt][0], 0.f) + wc1 * fmaxf(acc[mt][nt][1], 0.f);
                s[mt][1] += wc0 * fmaxf(acc[mt][nt][2], 0.f) + wc1 * fmaxf(acc[mt][nt][3], 0.f);
            }
        }
#pragma unroll
        for (int d = 1; d <= 2; d <<= 1)
#pragma unroll
            for (int mt = 0; mt < 4; mt++) {
                s[mt][0] += __shfl_xor_sync(0xFFFFFFFFu, s[mt][0], d);
                s[mt][1] += __shfl_xor_sync(0xFFFFFFFFu, s[mt][1], d);
            }
        __syncthreads();
        if (la == 0) {
#pragma unroll
            for (int mt = 0; mt < 4; mt++) {
                const int px = mg * 64 + mt * 16 + r;
                sm[W_RED + ng * 128 + px] = s[mt][0];
                sm[W_RED + ng * 128 + px + 8] = s[mt][1];
            }
        }
        __syncthreads();
        if (t < 128) {
            float v = sm[W_RED + t] + sm[W_RED + 128 + t]
                    + sm[W_RED + 256 + t] + sm[W_RED + 384 + t] + bcls[0];
            out[(size_t)n * HWP + px0 + t] = v;
        }
    }
}

// ---------------- launch ----------------
extern "C" void kernel_launch(void* const* d_in, const int* in_sizes, int n_in,
                              void* d_out, int out_size) {
    const float* x      = (const float*)d_in[0];
    const float* offset = (const float*)d_in[1];
    const float* w_def  = (const float*)d_in[2];
    const float* w_cls  = (const float*)d_in[3];
    const float* b_cls  = (const float*)d_in[4];
    float* out = (float*)d_out;

    dim3 g1(HWP / 32, CC / 32, NN), b1(32, 8);
    transpose_x_kernel<<<g1, b1>>>(x);
    wprep_kernel<<<(NCHUNK * 256 * 16 + 255) / 256, 256>>>(w_def);

    cudaFuncSetAttribute(deform_mma_kernel,
                         cudaFuncAttributeMaxDynamicSharedMemorySize, SMEM_BYTES);
    deform_mma_kernel<<<NN * 32, 256, SMEM_BYTES>>>(offset, w_cls, b_cls, out);
}

// round 7
// speedup vs baseline: 3.3986x; 1.7046x over previous
#include <cuda_runtime.h>
#include <cuda_fp16.h>
#include <cstdint>
#include <math.h>

#define NN 16
#define CC 256
#define OO 256
#define HWP 4096
#define NCHUNK 72          // 9 taps x 8 chunks of 32 channels

__device__ float g_xT[(size_t)NN * HWP * CC];   // NHWC f32 input
__device__ float g_wH[(size_t)NCHUNK * 8704];   // per chunk: Bh[256o][17] fp16x2, Bl at +4352

// ---------------- helpers ----------------
__device__ __forceinline__ uint32_t smem_u32(const void* p) {
    uint32_t a;
    asm("{ .reg .u64 t; cvta.to.shared.u64 t, %1; cvt.u32.u64 %0, t; }" : "=r"(a) : "l"(p));
    return a;
}
__device__ __forceinline__ void cp_async16(uint32_t d, const void* s) {
    asm volatile("cp.async.ca.shared.global [%0], [%1], 16;" :: "r"(d), "l"(s));
}
#define CP_COMMIT() asm volatile("cp.async.commit_group;" ::: "memory")
#define CP_WAIT0()  asm volatile("cp.async.wait_group 0;" ::: "memory")

__device__ __forceinline__ void mma16816(float* c, uint32_t a0, uint32_t a1,
                                         uint32_t a2, uint32_t a3,
                                         uint32_t b0, uint32_t b1) {
    asm volatile(
        "mma.sync.aligned.m16n8k16.row.col.f32.f16.f16.f32 "
        "{%0,%1,%2,%3}, {%4,%5,%6,%7}, {%8,%9}, {%0,%1,%2,%3};"
        : "+f"(c[0]), "+f"(c[1]), "+f"(c[2]), "+f"(c[3])
        : "r"(a0), "r"(a1), "r"(a2), "r"(a3), "r"(b0), "r"(b1));
}

// ---------------- kernel 1: NCHW -> NHWC ----------------
__global__ void transpose_x_kernel(const float* __restrict__ x) {
    __shared__ float tile[32][33];
    const int n = blockIdx.z, s0 = blockIdx.x * 32, c0 = blockIdx.y * 32;
    const int tx = threadIdx.x, ty = threadIdx.y;
    const float* xp = x + (size_t)n * CC * HWP;
#pragma unroll
    for (int j = 0; j < 4; j++)
        tile[ty + j * 8][tx] = xp[(size_t)(c0 + ty + j * 8) * HWP + s0 + tx];
    __syncthreads();
    float* xt = g_xT + (size_t)n * HWP * CC;
#pragma unroll
    for (int j = 0; j < 4; j++)
        xt[(size_t)(s0 + ty + j * 8) * CC + c0 + tx] = tile[tx][ty + j * 8];
}

// ---------------- kernel 2: weight fp16 hi/lo split, stride-17 pair layout ----------------
__global__ void wprep_kernel(const float* __restrict__ wdef) {
    int idx = blockIdx.x * blockDim.x + threadIdx.x;
    if (idx >= NCHUNK * 256 * 16) return;
    int p = idx & 15, o = (idx >> 4) & 255, chunk = idx >> 12;
    int tap = chunk >> 3, cgrp = chunk & 7;
    int c0 = cgrp * 32 + 2 * p;
    float w0 = wdef[((size_t)o * CC + c0) * 9 + tap];
    float w1 = wdef[((size_t)o * CC + c0 + 1) * 9 + tap];
    __half h0 = __float2half_rn(w0), h1 = __float2half_rn(w1);
    __half l0 = __float2half_rn(w0 - __half2float(h0));
    __half l1 = __float2half_rn(w1 - __half2float(h1));
    float* dst = g_wH + (size_t)chunk * 8704;
    __half2 hp = __halves2half2(h0, h1);   // .x = h0 (low) = even channel
    __half2 lp = __halves2half2(l0, l1);
    dst[o * 17 + p] = __uint_as_float(*(uint32_t*)&hp);
    dst[4352 + o * 17 + p] = __uint_as_float(*(uint32_t*)&lp);
}

// ---------------- kernel 3: pipelined deform + fp16 mma GEMM + relu + cls ----------------
// SMEM word offsets
#define W_COORD 0                 // 2 x [128 px][8]  (tap parity double buffer)
#define W_RED   2048              // [4 ng][128 px]
#define W_A     2560              // 2 x [16 kpair][133] fp16x2  (chunk parity)
#define W_B     6816              // 2 x (Bh[4352] + Bl[4352])
#define SMEM_WORDS 24224
#define SMEM_BYTES (SMEM_WORDS * 4)   // 96896

__global__ void __launch_bounds__(256, 1)
deform_mma_kernel(const float* __restrict__ off, const float* __restrict__ wcls,
                  const float* __restrict__ bcls, float* __restrict__ out) {
    extern __shared__ float sm[];
    int* smi = (int*)sm;
    const uint32_t sb = smem_u32(sm);
    const int t = threadIdx.x, lane = t & 31, w = t >> 5;
    const int mg = w >> 2, ng = w & 3;
    const int n = blockIdx.x >> 5, pblk = blockIdx.x & 31;
    const int px0 = pblk * 128;
    const int l8 = t & 7, g = t >> 3;
    const int la = lane & 3, r = lane >> 2;
    const float* xb = g_xT + (size_t)n * HWP * CC;

    float acc[4][8][4];
#pragma unroll
    for (int a = 0; a < 4; a++)
#pragma unroll
        for (int b = 0; b < 8; b++)
#pragma unroll
            for (int c = 0; c < 4; c++) acc[a][b][c] = 0.f;

    // ---- coord compute (tap -> coord slot) ----
#define COORDS(TAP, BASE)                                                        \
    if (t < 128) {                                                               \
        const int gpix = px0 + t, hh = gpix >> 6, wx = gpix & 63;                \
        const float* op = off + (size_t)(n * HWP + gpix) * 18 + 2 * (TAP);       \
        const float dy = op[0], dx = op[1];                                      \
        const float py = (float)(hh + (TAP) / 3 - 1) + dy;                       \
        const float pxx = (float)(wx + (TAP) % 3 - 1) + dx;                      \
        const float y0f = floorf(py), x0f = floorf(pxx);                         \
        const float fy = py - y0f, fx = pxx - x0f;                               \
        const int y0 = (int)y0f, x0 = (int)x0f, y1 = y0 + 1, x1 = x0 + 1;        \
        float w00 = (1.f - fy) * (1.f - fx), w01 = (1.f - fy) * fx;              \
        float w10 = fy * (1.f - fx), w11 = fy * fx;                              \
        if (!((unsigned)y0 < 64u && (unsigned)x0 < 64u)) w00 = 0.f;              \
        if (!((unsigned)y0 < 64u && (unsigned)x1 < 64u)) w01 = 0.f;              \
        if (!((unsigned)y1 < 64u && (unsigned)x0 < 64u)) w10 = 0.f;              \
        if (!((unsigned)y1 < 64u && (unsigned)x1 < 64u)) w11 = 0.f;              \
        const int yc0 = min(max(y0, 0), 63), yc1 = min(max(y1, 0), 63);          \
        const int xc0 = min(max(x0, 0), 63), xc1 = min(max(x1, 0), 63);          \
        smi[(BASE) + t * 8 + 0] = (yc0 * 64 + xc0) * 256;                        \
        smi[(BASE) + t * 8 + 1] = (yc0 * 64 + xc1) * 256;                        \
        smi[(BASE) + t * 8 + 2] = (yc1 * 64 + xc0) * 256;                        \
        smi[(BASE) + t * 8 + 3] = (yc1 * 64 + xc1) * 256;                        \
        sm[(BASE) + t * 8 + 4] = w00; sm[(BASE) + t * 8 + 5] = w01;              \
        sm[(BASE) + t * 8 + 6] = w10; sm[(BASE) + t * 8 + 7] = w11;              \
    }

#define STAGE_B(CH, BUF) {                                                       \
        const float4* src = (const float4*)(g_wH + (size_t)(CH) * 8704);         \
        const uint32_t db = sb + (W_B + (BUF) * 8704) * 4;                       \
        _Pragma("unroll")                                                        \
        for (int i = 0; i < 8; i++)                                              \
            cp_async16(db + (uint32_t)(t + (i << 8)) * 16, src + t + (i << 8));  \
        if (t < 128) cp_async16(db + (uint32_t)(2048 + t) * 16, src + 2048 + t); \
    }

// NOTE: channel slot offset (l8*4) is applied HERE — this was the R6 bug.
#define GATHER_HALF(HF, CBASE, CB) {                                             \
        const int choff = (CB) + (l8 << 2);                                      \
        _Pragma("unroll")                                                        \
        for (int jj = 0; jj < 2; jj++) {                                         \
            const int px = g * 4 + (HF) * 2 + jj;                                \
            const int* ci = smi + (CBASE) + px * 8;                              \
            const float* cf = sm + (CBASE) + px * 8;                             \
            wv[jj][0] = cf[4]; wv[jj][1] = cf[5];                                \
            wv[jj][2] = cf[6]; wv[jj][3] = cf[7];                                \
            ga[jj][0] = *(const float4*)(xb + ci[0] + choff);                    \
            ga[jj][1] = *(const float4*)(xb + ci[1] + choff);                    \
            ga[jj][2] = *(const float4*)(xb + ci[2] + choff);                    \
            ga[jj][3] = *(const float4*)(xb + ci[3] + choff);                    \
        }                                                                        \
    }

#define COMBINE_HALF(HF, ABASE) {                                                \
        _Pragma("unroll")                                                        \
        for (int jj = 0; jj < 2; jj++) {                                         \
            const int px = g * 4 + (HF) * 2 + jj;                                \
            float v0 = wv[jj][0] * ga[jj][0].x + wv[jj][1] * ga[jj][1].x         \
                     + wv[jj][2] * ga[jj][2].x + wv[jj][3] * ga[jj][3].x;        \
            float v1 = wv[jj][0] * ga[jj][0].y + wv[jj][1] * ga[jj][1].y         \
                     + wv[jj][2] * ga[jj][2].y + wv[jj][3] * ga[jj][3].y;        \
            float v2 = wv[jj][0] * ga[jj][0].z + wv[jj][1] * ga[jj][1].z         \
                     + wv[jj][2] * ga[jj][2].z + wv[jj][3] * ga[jj][3].z;        \
            float v3 = wv[jj][0] * ga[jj][0].w + wv[jj][1] * ga[jj][1].w         \
                     + wv[jj][2] * ga[jj][2].w + wv[jj][3] * ga[jj][3].w;        \
            __half2 p01 = __floats2half2_rn(v0, v1);                             \
            __half2 p23 = __floats2half2_rn(v2, v3);                             \
            sm[(ABASE) + (2 * l8) * 133 + px]     = __uint_as_float(*(uint32_t*)&p01); \
            sm[(ABASE) + (2 * l8 + 1) * 133 + px] = __uint_as_float(*(uint32_t*)&p23); \
        }                                                                        \
    }

#define MMA_KT(KT, ABASE, BBASE) {                                               \
        const uint32_t* Ah = (const uint32_t*)(sm + (ABASE));                    \
        const uint32_t* Bh = (const uint32_t*)(sm + (BBASE));                    \
        const uint32_t* Bl = Bh + 4352;                                          \
        uint32_t af[4][4];                                                       \
        const int pa = (KT) * 8 + la;                                            \
        _Pragma("unroll")                                                        \
        for (int mt = 0; mt < 4; mt++) {                                         \
            const int base = pa * 133 + mg * 64 + mt * 16 + r;                   \
            af[mt][0] = Ah[base];           af[mt][1] = Ah[base + 8];            \
            af[mt][2] = Ah[base + 4 * 133]; af[mt][3] = Ah[base + 4 * 133 + 8];  \
        }                                                                        \
        _Pragma("unroll")                                                        \
        for (int nt = 0; nt < 8; nt++) {                                         \
            const int ob = (ng * 64 + nt * 8 + r) * 17 + (KT) * 8 + la;          \
            const uint32_t bh0 = Bh[ob], bh1 = Bh[ob + 4];                       \
            const uint32_t bl0 = Bl[ob], bl1 = Bl[ob + 4];                       \
            _Pragma("unroll")                                                    \
            for (int mt = 0; mt < 4; mt++) {                                     \
                mma16816(acc[mt][nt], af[mt][0], af[mt][1], af[mt][2], af[mt][3], bh0, bh1); \
                mma16816(acc[mt][nt], af[mt][0], af[mt][1], af[mt][2], af[mt][3], bl0, bl1); \
            }                                                                    \
        }                                                                        \
    }

    float4 ga[2][4];
    float wv[2][4];

    // ---------------- prologue ----------------
    COORDS(0, W_COORD);
    __syncthreads();
    STAGE_B(0, 0);
    CP_COMMIT();
    GATHER_HALF(0, W_COORD, 0);
    COMBINE_HALF(0, W_A);
    GATHER_HALF(1, W_COORD, 0);
    COMBINE_HALF(1, W_A);
    CP_WAIT0();
    __syncthreads();

    // ---------------- main loop ----------------
#pragma unroll 1
    for (int k = 0; k < NCHUNK; ++k) {
        const int buf = k & 1, nbuf = buf ^ 1;
        const bool nx = (k + 1 < NCHUNK);
        const int abase = W_A + buf * 2128, bbase = W_B + buf * 8704;
        const int anext = W_A + nbuf * 2128;
        const int tapN = (k + 1) >> 3;
        const int cbase = W_COORD + (tapN & 1) * 1024;
        const int cbch = ((k + 1) & 7) << 5;

        if (nx) STAGE_B(k + 1, nbuf);
        CP_COMMIT();

        if (nx) GATHER_HALF(0, cbase, cbch);
        MMA_KT(0, abase, bbase);
        if (nx) COMBINE_HALF(0, anext);

        if (nx) GATHER_HALF(1, cbase, cbch);
        MMA_KT(1, abase, bbase);
        if (nx) COMBINE_HALF(1, anext);

        if (((k + 2) & 7) == 0 && (k + 2) < NCHUNK) {
            const int t2 = (k + 2) >> 3;
            COORDS(t2, W_COORD + (t2 & 1) * 1024);
        }
        CP_WAIT0();
        __syncthreads();
    }

    // ---------------- epilogue: relu + wcls dot, reduce over o ----------------
    {
        float s[4][2];
#pragma unroll
        for (int mt = 0; mt < 4; mt++) { s[mt][0] = 0.f; s[mt][1] = 0.f; }
#pragma unroll
        for (int nt = 0; nt < 8; nt++) {
            const int col = ng * 64 + nt * 8 + 2 * la;
            const float wc0 = __ldg(&wcls[col]), wc1 = __ldg(&wcls[col + 1]);
#pragma unroll
            for (int mt = 0; mt < 4; mt++) {
                s[mt][0] += wc0 * fmaxf(acc[mt][nt][0], 0.f) + wc1 * fmaxf(acc[mt][nt][1], 0.f);
                s[mt][1] += wc0 * fmaxf(acc[mt][nt][2], 0.f) + wc1 * fmaxf(acc[mt][nt][3], 0.f);
            }
        }
#pragma unroll
        for (int d = 1; d <= 2; d <<= 1)
#pragma unroll
            for (int mt = 0; mt < 4; mt++) {
                s[mt][0] += __shfl_xor_sync(0xFFFFFFFFu, s[mt][0], d);
                s[mt][1] += __shfl_xor_sync(0xFFFFFFFFu, s[mt][1], d);
            }
        __syncthreads();
        if (la == 0) {
#pragma unroll
            for (int mt = 0; mt < 4; mt++) {
                const int px = mg * 64 + mt * 16 + r;
                sm[W_RED + ng * 128 + px] = s[mt][0];
                sm[W_RED + ng * 128 + px + 8] = s[mt][1];
            }
        }
        __syncthreads();
        if (t < 128) {
            out[(size_t)n * HWP + px0 + t] =
                sm[W_RED + t] + sm[W_RED + 128 + t] +
                sm[W_RED + 256 + t] + sm[W_RED + 384 + t] + bcls[0];
        }
    }
}

// ---------------- launch ----------------
extern "C" void kernel_launch(void* const* d_in, const int* in_sizes, int n_in,
                              void* d_out, int out_size) {
    const float* x      = (const float*)d_in[0];
    const float* offset = (const float*)d_in[1];
    const float* w_def  = (const float*)d_in[2];
    const float* w_cls  = (const float*)d_in[3];
    const float* b_cls  = (const float*)d_in[4];
    float* out = (float*)d_out;

    dim3 g1(HWP / 32, CC / 32, NN), b1(32, 8);
    transpose_x_kernel<<<g1, b1>>>(x);
    wprep_kernel<<<(NCHUNK * 256 * 16 + 255) / 256, 256>>>(w_def);

    cudaFuncSetAttribute(deform_mma_kernel,
                         cudaFuncAttributeMaxDynamicSharedMemorySize, SMEM_BYTES);
    deform_mma_kernel<<<NN * 32, 256, SMEM_BYTES>>>(offset, w_cls, b_cls, out);
}

// round 8
// speedup vs baseline: 4.4628x; 1.3131x over previous
#include <cuda_runtime.h>
#include <cuda_fp16.h>
#include <cstdint>
#include <math.h>

#define NN 16
#define CC 256
#define OO 256
#define HWP 4096
#define NCHUNK 72          // 9 taps x 8 chunks of 32 channels

__device__ float g_xT[(size_t)NN * HWP * CC];   // NHWC f32 input
__device__ float g_wH[(size_t)NCHUNK * 4352];   // per chunk: Bh[256o][17] fp16x2

// ---------------- helpers ----------------
__device__ __forceinline__ uint32_t smem_u32(const void* p) {
    uint32_t a;
    asm("{ .reg .u64 t; cvta.to.shared.u64 t, %1; cvt.u32.u64 %0, t; }" : "=r"(a) : "l"(p));
    return a;
}
__device__ __forceinline__ void cp_async16(uint32_t d, const void* s) {
    asm volatile("cp.async.ca.shared.global [%0], [%1], 16;" :: "r"(d), "l"(s));
}
#define CP_COMMIT() asm volatile("cp.async.commit_group;" ::: "memory")
#define CP_WAIT0()  asm volatile("cp.async.wait_group 0;" ::: "memory")

__device__ __forceinline__ void mma16816(float* c, uint32_t a0, uint32_t a1,
                                         uint32_t a2, uint32_t a3,
                                         uint32_t b0, uint32_t b1) {
    asm volatile(
        "mma.sync.aligned.m16n8k16.row.col.f32.f16.f16.f32 "
        "{%0,%1,%2,%3}, {%4,%5,%6,%7}, {%8,%9}, {%0,%1,%2,%3};"
        : "+f"(c[0]), "+f"(c[1]), "+f"(c[2]), "+f"(c[3])
        : "r"(a0), "r"(a1), "r"(a2), "r"(a3), "r"(b0), "r"(b1));
}

// ---------------- kernel 1: NCHW -> NHWC ----------------
__global__ void transpose_x_kernel(const float* __restrict__ x) {
    __shared__ float tile[32][33];
    const int n = blockIdx.z, s0 = blockIdx.x * 32, c0 = blockIdx.y * 32;
    const int tx = threadIdx.x, ty = threadIdx.y;
    const float* xp = x + (size_t)n * CC * HWP;
#pragma unroll
    for (int j = 0; j < 4; j++)
        tile[ty + j * 8][tx] = xp[(size_t)(c0 + ty + j * 8) * HWP + s0 + tx];
    __syncthreads();
    float* xt = g_xT + (size_t)n * HWP * CC;
#pragma unroll
    for (int j = 0; j < 4; j++)
        xt[(size_t)(s0 + ty + j * 8) * CC + c0 + tx] = tile[tx][ty + j * 8];
}

// ---------------- kernel 2: weight fp16, stride-17 pair layout ----------------
__global__ void wprep_kernel(const float* __restrict__ wdef) {
    int idx = blockIdx.x * blockDim.x + threadIdx.x;
    if (idx >= NCHUNK * 256 * 16) return;
    int p = idx & 15, o = (idx >> 4) & 255, chunk = idx >> 12;
    int tap = chunk >> 3, cgrp = chunk & 7;
    int c0 = cgrp * 32 + 2 * p;
    float w0 = wdef[((size_t)o * CC + c0) * 9 + tap];
    float w1 = wdef[((size_t)o * CC + c0 + 1) * 9 + tap];
    __half2 hp = __halves2half2(__float2half_rn(w0), __float2half_rn(w1));
    g_wH[(size_t)chunk * 4352 + o * 17 + p] = __uint_as_float(*(uint32_t*)&hp);
}

// ---------------- kernel 3: pipelined deform + fp16 mma GEMM + relu + cls ----------------
// SMEM word offsets
#define W_COORD 0                 // 2 x [128 px][8]  (tap parity double buffer)
#define W_RED   2048              // [4 ng][128 px]
#define W_A     2560              // 2 x [16 kpair][133] fp16x2  (chunk parity)
#define W_B     6816              // 2 x Bh[4352]
#define SMEM_WORDS 15520
#define SMEM_BYTES (SMEM_WORDS * 4)   // 62080

__global__ void __launch_bounds__(256, 1)
deform_mma_kernel(const float* __restrict__ off, const float* __restrict__ wcls,
                  const float* __restrict__ bcls, float* __restrict__ out) {
    extern __shared__ float sm[];
    int* smi = (int*)sm;
    const uint32_t sb = smem_u32(sm);
    const int t = threadIdx.x, lane = t & 31, w = t >> 5;
    const int mg = w >> 2, ng = w & 3;
    const int n = blockIdx.x >> 5, pblk = blockIdx.x & 31;
    const int px0 = pblk * 128;
    const int l8 = t & 7, g = t >> 3;
    const int la = lane & 3, r = lane >> 2;
    const float* xb = g_xT + (size_t)n * HWP * CC;

    float acc[4][8][4];
#pragma unroll
    for (int a = 0; a < 4; a++)
#pragma unroll
        for (int b = 0; b < 8; b++)
#pragma unroll
            for (int c = 0; c < 4; c++) acc[a][b][c] = 0.f;

    // ---- coord compute (tap -> coord slot) ----
#define COORDS(TAP, BASE)                                                        \
    if (t < 128) {                                                               \
        const int gpix = px0 + t, hh = gpix >> 6, wx = gpix & 63;                \
        const float* op = off + (size_t)(n * HWP + gpix) * 18 + 2 * (TAP);       \
        const float dy = op[0], dx = op[1];                                      \
        const float py = (float)(hh + (TAP) / 3 - 1) + dy;                       \
        const float pxx = (float)(wx + (TAP) % 3 - 1) + dx;                      \
        const float y0f = floorf(py), x0f = floorf(pxx);                         \
        const float fy = py - y0f, fx = pxx - x0f;                               \
        const int y0 = (int)y0f, x0 = (int)x0f, y1 = y0 + 1, x1 = x0 + 1;        \
        float w00 = (1.f - fy) * (1.f - fx), w01 = (1.f - fy) * fx;              \
        float w10 = fy * (1.f - fx), w11 = fy * fx;                              \
        if (!((unsigned)y0 < 64u && (unsigned)x0 < 64u)) w00 = 0.f;              \
        if (!((unsigned)y0 < 64u && (unsigned)x1 < 64u)) w01 = 0.f;              \
        if (!((unsigned)y1 < 64u && (unsigned)x0 < 64u)) w10 = 0.f;              \
        if (!((unsigned)y1 < 64u && (unsigned)x1 < 64u)) w11 = 0.f;              \
        const int yc0 = min(max(y0, 0), 63), yc1 = min(max(y1, 0), 63);          \
        const int xc0 = min(max(x0, 0), 63), xc1 = min(max(x1, 0), 63);          \
        smi[(BASE) + t * 8 + 0] = (yc0 * 64 + xc0) * 256;                        \
        smi[(BASE) + t * 8 + 1] = (yc0 * 64 + xc1) * 256;                        \
        smi[(BASE) + t * 8 + 2] = (yc1 * 64 + xc0) * 256;                        \
        smi[(BASE) + t * 8 + 3] = (yc1 * 64 + xc1) * 256;                        \
        sm[(BASE) + t * 8 + 4] = w00; sm[(BASE) + t * 8 + 5] = w01;              \
        sm[(BASE) + t * 8 + 6] = w10; sm[(BASE) + t * 8 + 7] = w11;              \
    }

#define STAGE_B(CH, BUF) {                                                       \
        const float4* src = (const float4*)(g_wH + (size_t)(CH) * 4352);         \
        const uint32_t db = sb + (W_B + (BUF) * 4352) * 4;                       \
        _Pragma("unroll")                                                        \
        for (int i = 0; i < 4; i++)                                              \
            cp_async16(db + (uint32_t)(t + (i << 8)) * 16, src + t + (i << 8));  \
        if (t < 64) cp_async16(db + (uint32_t)(1024 + t) * 16, src + 1024 + t);  \
    }

// channel slot offset (l8*4) applied here
#define GATHER_HALF(HF, CBASE, CB) {                                             \
        const int choff = (CB) + (l8 << 2);                                      \
        _Pragma("unroll")                                                        \
        for (int jj = 0; jj < 2; jj++) {                                         \
            const int px = g * 4 + (HF) * 2 + jj;                                \
            const int* ci = smi + (CBASE) + px * 8;                              \
            const float* cf = sm + (CBASE) + px * 8;                             \
            wv[jj][0] = cf[4]; wv[jj][1] = cf[5];                                \
            wv[jj][2] = cf[6]; wv[jj][3] = cf[7];                                \
            ga[jj][0] = *(const float4*)(xb + ci[0] + choff);                    \
            ga[jj][1] = *(const float4*)(xb + ci[1] + choff);                    \
            ga[jj][2] = *(const float4*)(xb + ci[2] + choff);                    \
            ga[jj][3] = *(const float4*)(xb + ci[3] + choff);                    \
        }                                                                        \
    }

#define COMBINE_HALF(HF, ABASE) {                                                \
        _Pragma("unroll")                                                        \
        for (int jj = 0; jj < 2; jj++) {                                         \
            const int px = g * 4 + (HF) * 2 + jj;                                \
            float v0 = wv[jj][0] * ga[jj][0].x + wv[jj][1] * ga[jj][1].x         \
                     + wv[jj][2] * ga[jj][2].x + wv[jj][3] * ga[jj][3].x;        \
            float v1 = wv[jj][0] * ga[jj][0].y + wv[jj][1] * ga[jj][1].y         \
                     + wv[jj][2] * ga[jj][2].y + wv[jj][3] * ga[jj][3].y;        \
            float v2 = wv[jj][0] * ga[jj][0].z + wv[jj][1] * ga[jj][1].z         \
                     + wv[jj][2] * ga[jj][2].z + wv[jj][3] * ga[jj][3].z;        \
            float v3 = wv[jj][0] * ga[jj][0].w + wv[jj][1] * ga[jj][1].w         \
                     + wv[jj][2] * ga[jj][2].w + wv[jj][3] * ga[jj][3].w;        \
            __half2 p01 = __floats2half2_rn(v0, v1);                             \
            __half2 p23 = __floats2half2_rn(v2, v3);                             \
            sm[(ABASE) + (2 * l8) * 133 + px]     = __uint_as_float(*(uint32_t*)&p01); \
            sm[(ABASE) + (2 * l8 + 1) * 133 + px] = __uint_as_float(*(uint32_t*)&p23); \
        }                                                                        \
    }

#define MMA_KT(KT, ABASE, BBASE) {                                               \
        const uint32_t* Ah = (const uint32_t*)(sm + (ABASE));                    \
        const uint32_t* Bh = (const uint32_t*)(sm + (BBASE));                    \
        uint32_t af[4][4];                                                       \
        const int pa = (KT) * 8 + la;                                            \
        _Pragma("unroll")                                                        \
        for (int mt = 0; mt < 4; mt++) {                                         \
            const int base = pa * 133 + mg * 64 + mt * 16 + r;                   \
            af[mt][0] = Ah[base];           af[mt][1] = Ah[base + 8];            \
            af[mt][2] = Ah[base + 4 * 133]; af[mt][3] = Ah[base + 4 * 133 + 8];  \
        }                                                                        \
        _Pragma("unroll")                                                        \
        for (int nt = 0; nt < 8; nt++) {                                         \
            const int ob = (ng * 64 + nt * 8 + r) * 17 + (KT) * 8 + la;          \
            const uint32_t bh0 = Bh[ob], bh1 = Bh[ob + 4];                       \
            _Pragma("unroll")                                                    \
            for (int mt = 0; mt < 4; mt++) {                                     \
                mma16816(acc[mt][nt], af[mt][0], af[mt][1], af[mt][2], af[mt][3], bh0, bh1); \
            }                                                                    \
        }                                                                        \
    }

    float4 ga[2][4];
    float wv[2][4];

    // ---------------- prologue ----------------
    COORDS(0, W_COORD);
    __syncthreads();
    STAGE_B(0, 0);
    CP_COMMIT();
    GATHER_HALF(0, W_COORD, 0);
    COMBINE_HALF(0, W_A);
    GATHER_HALF(1, W_COORD, 0);
    COMBINE_HALF(1, W_A);
    CP_WAIT0();
    __syncthreads();

    // ---------------- main loop ----------------
#pragma unroll 1
    for (int k = 0; k < NCHUNK; ++k) {
        const int buf = k & 1, nbuf = buf ^ 1;
        const bool nx = (k + 1 < NCHUNK);
        const int abase = W_A + buf * 2128, bbase = W_B + buf * 4352;
        const int anext = W_A + nbuf * 2128;
        const int tapN = (k + 1) >> 3;
        const int cbase = W_COORD + (tapN & 1) * 1024;
        const int cbch = ((k + 1) & 7) << 5;

        if (nx) STAGE_B(k + 1, nbuf);
        CP_COMMIT();

        if (nx) GATHER_HALF(0, cbase, cbch);
        MMA_KT(0, abase, bbase);
        if (nx) COMBINE_HALF(0, anext);

        if (nx) GATHER_HALF(1, cbase, cbch);
        MMA_KT(1, abase, bbase);
        if (nx) COMBINE_HALF(1, anext);

        if (((k + 2) & 7) == 0 && (k + 2) < NCHUNK) {
            const int t2 = (k + 2) >> 3;
            COORDS(t2, W_COORD + (t2 & 1) * 1024);
        }
        CP_WAIT0();
        __syncthreads();
    }

    // ---------------- epilogue: relu + wcls dot, reduce over o ----------------
    {
        float s[4][2];
#pragma unroll
        for (int mt = 0; mt < 4; mt++) { s[mt][0] = 0.f; s[mt][1] = 0.f; }
#pragma unroll
        for (int nt = 0; nt < 8; nt++) {
            const int col = ng * 64 + nt * 8 + 2 * la;
            const float wc0 = __ldg(&wcls[col]), wc1 = __ldg(&wcls[col + 1]);
#pragma unroll
            for (int mt = 0; mt < 4; mt++) {
                s[mt][0] += wc0 * fmaxf(acc[mt][nt][0], 0.f) + wc1 * fmaxf(acc[mt][nt][1], 0.f);
                s[mt][1] += wc0 * fmaxf(acc[mt][nt][2], 0.f) + wc1 * fmaxf(acc[mt][nt][3], 0.f);
            }
        }
#pragma unroll
        for (int d = 1; d <= 2; d <<= 1)
#pragma unroll
            for (int mt = 0; mt < 4; mt++) {
                s[mt][0] += __shfl_xor_sync(0xFFFFFFFFu, s[mt][0], d);
                s[mt][1] += __shfl_xor_sync(0xFFFFFFFFu, s[mt][1], d);
            }
        __syncthreads();
        if (la == 0) {
#pragma unroll
            for (int mt = 0; mt < 4; mt++) {
                const int px = mg * 64 + mt * 16 + r;
                sm[W_RED + ng * 128 + px] = s[mt][0];
                sm[W_RED + ng * 128 + px + 8] = s[mt][1];
            }
        }
        __syncthreads();
        if (t < 128) {
            out[(size_t)n * HWP + px0 + t] =
                sm[W_RED + t] + sm[W_RED + 128 + t] +
                sm[W_RED + 256 + t] + sm[W_RED + 384 + t] + bcls[0];
        }
    }
}

// ---------------- launch ----------------
extern "C" void kernel_launch(void* const* d_in, const int* in_sizes, int n_in,
                              void* d_out, int out_size) {
    const float* x      = (const float*)d_in[0];
    const float* offset = (const float*)d_in[1];
    const float* w_def  = (const float*)d_in[2];
    const float* w_cls  = (const float*)d_in[3];
    const float* b_cls  = (const float*)d_in[4];
    float* out = (float*)d_out;

    dim3 g1(HWP / 32, CC / 32, NN), b1(32, 8);
    transpose_x_kernel<<<g1, b1>>>(x);
    wprep_kernel<<<(NCHUNK * 256 * 16 + 255) / 256, 256>>>(w_def);

    cudaFuncSetAttribute(deform_mma_kernel,
                         cudaFuncAttributeMaxDynamicSharedMemorySize, SMEM_BYTES);
    deform_mma_kernel<<<NN * 32, 256, SMEM_BYTES>>>(offset, w_cls, b_cls, out);
}

// round 9
// speedup vs baseline: 4.8230x; 1.0807x over previous
#include <cuda_runtime.h>
#include <cuda_fp16.h>
#include <cstdint>
#include <math.h>

#define NN 16
#define CC 256
#define OO 256
#define HWP 4096
#define NCHUNK 72          // 9 taps x 8 chunks of 32 channels

__device__ __half g_xT[(size_t)NN * HWP * CC];  // NHWC fp16 input (33.5 MB)
__device__ float g_wH[(size_t)NCHUNK * 4352];   // per chunk: Bh[256o][17] fp16x2

// ---------------- helpers ----------------
__device__ __forceinline__ uint32_t smem_u32(const void* p) {
    uint32_t a;
    asm("{ .reg .u64 t; cvta.to.shared.u64 t, %1; cvt.u32.u64 %0, t; }" : "=r"(a) : "l"(p));
    return a;
}
__device__ __forceinline__ void cp_async16(uint32_t d, const void* s) {
    asm volatile("cp.async.ca.shared.global [%0], [%1], 16;" :: "r"(d), "l"(s));
}
#define CP_COMMIT() asm volatile("cp.async.commit_group;" ::: "memory")
#define CP_WAIT0()  asm volatile("cp.async.wait_group 0;" ::: "memory")

__device__ __forceinline__ __half2 u2h(uint32_t v) { return *(__half2*)&v; }
__device__ __forceinline__ uint32_t h2u(__half2 v) { return *(uint32_t*)&v; }

__device__ __forceinline__ void mma16816(float* c, uint32_t a0, uint32_t a1,
                                         uint32_t a2, uint32_t a3,
                                         uint32_t b0, uint32_t b1) {
    asm volatile(
        "mma.sync.aligned.m16n8k16.row.col.f32.f16.f16.f32 "
        "{%0,%1,%2,%3}, {%4,%5,%6,%7}, {%8,%9}, {%0,%1,%2,%3};"
        : "+f"(c[0]), "+f"(c[1]), "+f"(c[2]), "+f"(c[3])
        : "r"(a0), "r"(a1), "r"(a2), "r"(a3), "r"(b0), "r"(b1));
}

// ---------------- kernel 1: NCHW f32 -> NHWC fp16 ----------------
__global__ void transpose_x_kernel(const float* __restrict__ x) {
    __shared__ float tile[64][33];
    const int n = blockIdx.z, s0 = blockIdx.x * 32, c0 = blockIdx.y * 64;
    const int tx = threadIdx.x, ty = threadIdx.y;   // (32, 8)
    const float* xp = x + (size_t)n * CC * HWP;
#pragma unroll
    for (int j = 0; j < 8; j++)
        tile[ty + j * 8][tx] = xp[(size_t)(c0 + ty + j * 8) * HWP + s0 + tx];
    __syncthreads();
    __half* xt = g_xT + (size_t)n * HWP * CC;
#pragma unroll
    for (int j = 0; j < 4; j++) {
        const int s = ty + j * 8;
        __half2 hv = __floats2half2_rn(tile[2 * tx][s], tile[2 * tx + 1][s]);
        *(__half2*)(xt + (size_t)(s0 + s) * CC + c0 + 2 * tx) = hv;
    }
}

// ---------------- kernel 2: weight fp16, stride-17 pair layout ----------------
__global__ void wprep_kernel(const float* __restrict__ wdef) {
    int idx = blockIdx.x * blockDim.x + threadIdx.x;
    if (idx >= NCHUNK * 256 * 16) return;
    int p = idx & 15, o = (idx >> 4) & 255, chunk = idx >> 12;
    int tap = chunk >> 3, cgrp = chunk & 7;
    int c0 = cgrp * 32 + 2 * p;
    float w0 = wdef[((size_t)o * CC + c0) * 9 + tap];
    float w1 = wdef[((size_t)o * CC + c0 + 1) * 9 + tap];
    __half2 hp = __halves2half2(__float2half_rn(w0), __float2half_rn(w1));
    g_wH[(size_t)chunk * 4352 + o * 17 + p] = __uint_as_float(h2u(hp));
}

// ---------------- kernel 3: pipelined deform + fp16 mma GEMM + relu + cls ----------------
// SMEM word offsets
#define W_COORD 0                 // 2 x [128 px][8]  (tap parity double buffer)
#define W_RED   2048              // [4 ng][128 px]
#define W_A     2560              // 2 x [16 kpair][133] fp16x2  (chunk parity)
#define W_B     6816              // 2 x Bh[4352]
#define SMEM_WORDS 15520
#define SMEM_BYTES (SMEM_WORDS * 4)   // 62080

__global__ void __launch_bounds__(256, 1)
deform_mma_kernel(const float* __restrict__ off, const float* __restrict__ wcls,
                  const float* __restrict__ bcls, float* __restrict__ out) {
    extern __shared__ float sm[];
    int* smi = (int*)sm;
    const uint32_t sb = smem_u32(sm);
    const int t = threadIdx.x, lane = t & 31, w = t >> 5;
    const int mg = w >> 2, ng = w & 3;
    const int n = blockIdx.x >> 5, pblk = blockIdx.x & 31;
    const int px0 = pblk * 128;
    const int l8 = t & 7, g = t >> 3;
    const int la = lane & 3, r = lane >> 2;
    const __half* xb = g_xT + (size_t)n * HWP * CC;

    float acc[4][8][4];
#pragma unroll
    for (int a = 0; a < 4; a++)
#pragma unroll
        for (int b = 0; b < 8; b++)
#pragma unroll
            for (int c = 0; c < 4; c++) acc[a][b][c] = 0.f;

    // ---- coord compute (tap -> coord slot) ----
#define COORDS(TAP, BASE)                                                        \
    if (t < 128) {                                                               \
        const int gpix = px0 + t, hh = gpix >> 6, wx = gpix & 63;                \
        const float* op = off + (size_t)(n * HWP + gpix) * 18 + 2 * (TAP);       \
        const float dy = op[0], dx = op[1];                                      \
        const float py = (float)(hh + (TAP) / 3 - 1) + dy;                       \
        const float pxx = (float)(wx + (TAP) % 3 - 1) + dx;                      \
        const float y0f = floorf(py), x0f = floorf(pxx);                         \
        const float fy = py - y0f, fx = pxx - x0f;                               \
        const int y0 = (int)y0f, x0 = (int)x0f, y1 = y0 + 1, x1 = x0 + 1;        \
        float w00 = (1.f - fy) * (1.f - fx), w01 = (1.f - fy) * fx;              \
        float w10 = fy * (1.f - fx), w11 = fy * fx;                              \
        if (!((unsigned)y0 < 64u && (unsigned)x0 < 64u)) w00 = 0.f;              \
        if (!((unsigned)y0 < 64u && (unsigned)x1 < 64u)) w01 = 0.f;              \
        if (!((unsigned)y1 < 64u && (unsigned)x0 < 64u)) w10 = 0.f;              \
        if (!((unsigned)y1 < 64u && (unsigned)x1 < 64u)) w11 = 0.f;              \
        const int yc0 = min(max(y0, 0), 63), yc1 = min(max(y1, 0), 63);          \
        const int xc0 = min(max(x0, 0), 63), xc1 = min(max(x1, 0), 63);          \
        smi[(BASE) + t * 8 + 0] = (yc0 * 64 + xc0) * 256;                        \
        smi[(BASE) + t * 8 + 1] = (yc0 * 64 + xc1) * 256;                        \
        smi[(BASE) + t * 8 + 2] = (yc1 * 64 + xc0) * 256;                        \
        smi[(BASE) + t * 8 + 3] = (yc1 * 64 + xc1) * 256;                        \
        sm[(BASE) + t * 8 + 4] = w00; sm[(BASE) + t * 8 + 5] = w01;              \
        sm[(BASE) + t * 8 + 6] = w10; sm[(BASE) + t * 8 + 7] = w11;              \
    }

#define STAGE_B(CH, BUF) {                                                       \
        const float4* src = (const float4*)(g_wH + (size_t)(CH) * 4352);         \
        const uint32_t db = sb + (W_B + (BUF) * 4352) * 4;                       \
        _Pragma("unroll")                                                        \
        for (int i = 0; i < 4; i++)                                              \
            cp_async16(db + (uint32_t)(t + (i << 8)) * 16, src + t + (i << 8));  \
        if (t < 64) cp_async16(db + (uint32_t)(1024 + t) * 16, src + 1024 + t);  \
    }

// channel slot offset (l8*4) applied here; loads are 8B (4 fp16 channels)
#define GATHER_HALF(HF, CBASE, CB) {                                             \
        const int choff = (CB) + (l8 << 2);                                      \
        _Pragma("unroll")                                                        \
        for (int jj = 0; jj < 2; jj++) {                                         \
            const int px = g * 4 + (HF) * 2 + jj;                                \
            const int* ci = smi + (CBASE) + px * 8;                              \
            const float* cf = sm + (CBASE) + px * 8;                             \
            wh[jj][0] = __float2half2_rn(cf[4]);                                 \
            wh[jj][1] = __float2half2_rn(cf[5]);                                 \
            wh[jj][2] = __float2half2_rn(cf[6]);                                 \
            wh[jj][3] = __float2half2_rn(cf[7]);                                 \
            ha[jj][0] = *(const uint2*)(xb + ci[0] + choff);                     \
            ha[jj][1] = *(const uint2*)(xb + ci[1] + choff);                     \
            ha[jj][2] = *(const uint2*)(xb + ci[2] + choff);                     \
            ha[jj][3] = *(const uint2*)(xb + ci[3] + choff);                     \
        }                                                                        \
    }

#define COMBINE_HALF(HF, ABASE) {                                                \
        _Pragma("unroll")                                                        \
        for (int jj = 0; jj < 2; jj++) {                                         \
            const int px = g * 4 + (HF) * 2 + jj;                                \
            __half2 v01 = __hmul2(u2h(ha[jj][0].x), wh[jj][0]);                  \
            v01 = __hfma2(u2h(ha[jj][1].x), wh[jj][1], v01);                     \
            v01 = __hfma2(u2h(ha[jj][2].x), wh[jj][2], v01);                     \
            v01 = __hfma2(u2h(ha[jj][3].x), wh[jj][3], v01);                     \
            __half2 v23 = __hmul2(u2h(ha[jj][0].y), wh[jj][0]);                  \
            v23 = __hfma2(u2h(ha[jj][1].y), wh[jj][1], v23);                     \
            v23 = __hfma2(u2h(ha[jj][2].y), wh[jj][2], v23);                     \
            v23 = __hfma2(u2h(ha[jj][3].y), wh[jj][3], v23);                     \
            sm[(ABASE) + (2 * l8) * 133 + px]     = __uint_as_float(h2u(v01));   \
            sm[(ABASE) + (2 * l8 + 1) * 133 + px] = __uint_as_float(h2u(v23));   \
        }                                                                        \
    }

#define MMA_KT(KT, ABASE, BBASE) {                                               \
        const uint32_t* Ah = (const uint32_t*)(sm + (ABASE));                    \
        const uint32_t* Bh = (const uint32_t*)(sm + (BBASE));                    \
        uint32_t af[4][4];                                                       \
        const int pa = (KT) * 8 + la;                                            \
        _Pragma("unroll")                                                        \
        for (int mt = 0; mt < 4; mt++) {                                         \
            const int base = pa * 133 + mg * 64 + mt * 16 + r;                   \
            af[mt][0] = Ah[base];           af[mt][1] = Ah[base + 8];            \
            af[mt][2] = Ah[base + 4 * 133]; af[mt][3] = Ah[base + 4 * 133 + 8];  \
        }                                                                        \
        _Pragma("unroll")                                                        \
        for (int nt = 0; nt < 8; nt++) {                                         \
            const int ob = (ng * 64 + nt * 8 + r) * 17 + (KT) * 8 + la;          \
            const uint32_t bh0 = Bh[ob], bh1 = Bh[ob + 4];                       \
            _Pragma("unroll")                                                    \
            for (int mt = 0; mt < 4; mt++) {                                     \
                mma16816(acc[mt][nt], af[mt][0], af[mt][1], af[mt][2], af[mt][3], bh0, bh1); \
            }                                                                    \
        }                                                                        \
    }

    uint2 ha[2][4];
    __half2 wh[2][4];

    // ---------------- prologue ----------------
    COORDS(0, W_COORD);
    __syncthreads();
    STAGE_B(0, 0);
    CP_COMMIT();
    GATHER_HALF(0, W_COORD, 0);
    COMBINE_HALF(0, W_A);
    GATHER_HALF(1, W_COORD, 0);
    COMBINE_HALF(1, W_A);
    CP_WAIT0();
    __syncthreads();

    // ---------------- main loop ----------------
#pragma unroll 1
    for (int k = 0; k < NCHUNK; ++k) {
        const int buf = k & 1, nbuf = buf ^ 1;
        const bool nx = (k + 1 < NCHUNK);
        const int abase = W_A + buf * 2128, bbase = W_B + buf * 4352;
        const int anext = W_A + nbuf * 2128;
        const int tapN = (k + 1) >> 3;
        const int cbase = W_COORD + (tapN & 1) * 1024;
        const int cbch = ((k + 1) & 7) << 5;

        if (nx) STAGE_B(k + 1, nbuf);
        CP_COMMIT();

        if (nx) GATHER_HALF(0, cbase, cbch);
        MMA_KT(0, abase, bbase);
        if (nx) COMBINE_HALF(0, anext);

        if (nx) GATHER_HALF(1, cbase, cbch);
        MMA_KT(1, abase, bbase);
        if (nx) COMBINE_HALF(1, anext);

        if (((k + 2) & 7) == 0 && (k + 2) < NCHUNK) {
            const int t2 = (k + 2) >> 3;
            COORDS(t2, W_COORD + (t2 & 1) * 1024);
        }
        CP_WAIT0();
        __syncthreads();
    }

    // ---------------- epilogue: relu + wcls dot, reduce over o ----------------
    {
        float s[4][2];
#pragma unroll
        for (int mt = 0; mt < 4; mt++) { s[mt][0] = 0.f; s[mt][1] = 0.f; }
#pragma unroll
        for (int nt = 0; nt < 8; nt++) {
            const int col = ng * 64 + nt * 8 + 2 * la;
            const float wc0 = __ldg(&wcls[col]), wc1 = __ldg(&wcls[col + 1]);
#pragma unroll
            for (int mt = 0; mt < 4; mt++) {
                s[mt][0] += wc0 * fmaxf(acc[mt][nt][0], 0.f) + wc1 * fmaxf(acc[mt][nt][1], 0.f);
                s[mt][1] += wc0 * fmaxf(acc[mt][nt][2], 0.f) + wc1 * fmaxf(acc[mt][nt][3], 0.f);
            }
        }
#pragma unroll
        for (int d = 1; d <= 2; d <<= 1)
#pragma unroll
            for (int mt = 0; mt < 4; mt++) {
                s[mt][0] += __shfl_xor_sync(0xFFFFFFFFu, s[mt][0], d);
                s[mt][1] += __shfl_xor_sync(0xFFFFFFFFu, s[mt][1], d);
            }
        __syncthreads();
        if (la == 0) {
#pragma unroll
            for (int mt = 0; mt < 4; mt++) {
                const int px = mg * 64 + mt * 16 + r;
                sm[W_RED + ng * 128 + px] = s[mt][0];
                sm[W_RED + ng * 128 + px + 8] = s[mt][1];
            }
        }
        __syncthreads();
        if (t < 128) {
            out[(size_t)n * HWP + px0 + t] =
                sm[W_RED + t] + sm[W_RED + 128 + t] +
                sm[W_RED + 256 + t] + sm[W_RED + 384 + t] + bcls[0];
        }
    }
}

// ---------------- launch ----------------
extern "C" void kernel_launch(void* const* d_in, const int* in_sizes, int n_in,
                              void* d_out, int out_size) {
    const float* x      = (const float*)d_in[0];
    const float* offset = (const float*)d_in[1];
    const float* w_def  = (const float*)d_in[2];
    const float* w_cls  = (const float*)d_in[3];
    const float* b_cls  = (const float*)d_in[4];
    float* out = (float*)d_out;

    dim3 g1(HWP / 32, CC / 64, NN), b1(32, 8);
    transpose_x_kernel<<<g1, b1>>>(x);
    wprep_kernel<<<(NCHUNK * 256 * 16 + 255) / 256, 256>>>(w_def);

    cudaFuncSetAttribute(deform_mma_kernel,
                         cudaFuncAttributeMaxDynamicSharedMemorySize, SMEM_BYTES);
    deform_mma_kernel<<<NN * 32, 256, SMEM_BYTES>>>(offset, w_cls, b_cls, out);
}

// round 10
// speedup vs baseline: 5.1922x; 1.0766x over previous
#include <cuda_runtime.h>
#include <cuda_fp16.h>
#include <cstdint>
#include <math.h>

#define NN 16
#define CC 256
#define OO 256
#define HWP 4096
#define NCHUNK 72          // 9 taps x 8 chunks of 32 channels

__device__ __half g_xT[(size_t)NN * HWP * CC];  // NHWC fp16 input (33.5 MB)
__device__ float g_wH[(size_t)NCHUNK * 4352];   // per chunk: Bh[256o][17] fp16x2

// ---------------- helpers ----------------
__device__ __forceinline__ uint32_t smem_u32(const void* p) {
    uint32_t a;
    asm("{ .reg .u64 t; cvta.to.shared.u64 t, %1; cvt.u32.u64 %0, t; }" : "=r"(a) : "l"(p));
    return a;
}
__device__ __forceinline__ void cp_async16(uint32_t d, const void* s) {
    asm volatile("cp.async.ca.shared.global [%0], [%1], 16;" :: "r"(d), "l"(s));
}
#define CP_COMMIT() asm volatile("cp.async.commit_group;" ::: "memory")
#define CP_WAIT0()  asm volatile("cp.async.wait_group 0;" ::: "memory")

__device__ __forceinline__ __half2 u2h(uint32_t v) { return *(__half2*)&v; }
__device__ __forceinline__ uint32_t h2u(__half2 v) { return *(uint32_t*)&v; }

__device__ __forceinline__ void mma16816(float* c, uint32_t a0, uint32_t a1,
                                         uint32_t a2, uint32_t a3,
                                         uint32_t b0, uint32_t b1) {
    asm volatile(
        "mma.sync.aligned.m16n8k16.row.col.f32.f16.f16.f32 "
        "{%0,%1,%2,%3}, {%4,%5,%6,%7}, {%8,%9}, {%0,%1,%2,%3};"
        : "+f"(c[0]), "+f"(c[1]), "+f"(c[2]), "+f"(c[3])
        : "r"(a0), "r"(a1), "r"(a2), "r"(a3), "r"(b0), "r"(b1));
}

// ---------------- kernel 1: NCHW f32 -> NHWC fp16 ----------------
__global__ void transpose_x_kernel(const float* __restrict__ x) {
    __shared__ float tile[64][33];
    const int n = blockIdx.z, s0 = blockIdx.x * 32, c0 = blockIdx.y * 64;
    const int tx = threadIdx.x, ty = threadIdx.y;   // (32, 8)
    const float* xp = x + (size_t)n * CC * HWP;
#pragma unroll
    for (int j = 0; j < 8; j++)
        tile[ty + j * 8][tx] = xp[(size_t)(c0 + ty + j * 8) * HWP + s0 + tx];
    __syncthreads();
    __half* xt = g_xT + (size_t)n * HWP * CC;
#pragma unroll
    for (int j = 0; j < 4; j++) {
        const int s = ty + j * 8;
        __half2 hv = __floats2half2_rn(tile[2 * tx][s], tile[2 * tx + 1][s]);
        *(__half2*)(xt + (size_t)(s0 + s) * CC + c0 + 2 * tx) = hv;
    }
}

// ---------------- kernel 2: weight fp16, stride-17 pair layout ----------------
__global__ void wprep_kernel(const float* __restrict__ wdef) {
    int idx = blockIdx.x * blockDim.x + threadIdx.x;
    if (idx >= NCHUNK * 256 * 16) return;
    int p = idx & 15, o = (idx >> 4) & 255, chunk = idx >> 12;
    int tap = chunk >> 3, cgrp = chunk & 7;
    int c0 = cgrp * 32 + 2 * p;
    float w0 = wdef[((size_t)o * CC + c0) * 9 + tap];
    float w1 = wdef[((size_t)o * CC + c0 + 1) * 9 + tap];
    __half2 hp = __halves2half2(__float2half_rn(w0), __float2half_rn(w1));
    g_wH[(size_t)chunk * 4352 + o * 17 + p] = __uint_as_float(h2u(hp));
}

// ---------------- kernel 3: M=64 tiles, 2 CTAs/SM ----------------
// SMEM word offsets
#define W_COORD 0                 // 2 x [64 px][8]  (tap parity double buffer) = 1024
#define W_RED   1024              // [4 ng][64 px] = 256
#define W_A     1280              // 2 x [16 kpair][69] fp16x2 (chunk parity) = 2208
#define W_B     3488              // 2 x Bh[4352]
#define SMEM_WORDS 12192
#define SMEM_BYTES (SMEM_WORDS * 4)   // 48768

__global__ void __launch_bounds__(256, 2)
deform_mma_kernel(const float* __restrict__ off, const float* __restrict__ wcls,
                  const float* __restrict__ bcls, float* __restrict__ out) {
    extern __shared__ float sm[];
    int* smi = (int*)sm;
    const uint32_t sb = smem_u32(sm);
    const int t = threadIdx.x, lane = t & 31, w = t >> 5;
    const int mg = w >> 2, ng = w & 3;               // 2 m-groups x 4 n-groups
    const int n = blockIdx.x >> 6, pblk = blockIdx.x & 63;
    const int px0 = pblk * 64;
    const int l8 = t & 7, g = t >> 3;                // g: 0..31, covers px {2g, 2g+1}
    const int la = lane & 3, r = lane >> 2;
    const __half* xb = g_xT + (size_t)n * HWP * CC;

    float acc[2][8][4];
#pragma unroll
    for (int a = 0; a < 2; a++)
#pragma unroll
        for (int b = 0; b < 8; b++)
#pragma unroll
            for (int c = 0; c < 4; c++) acc[a][b][c] = 0.f;

#define COORDS(TAP, BASE)                                                        \
    if (t < 64) {                                                                \
        const int gpix = px0 + t, hh = gpix >> 6, wx = gpix & 63;                \
        const float* op = off + (size_t)(n * HWP + gpix) * 18 + 2 * (TAP);       \
        const float dy = op[0], dx = op[1];                                      \
        const float py = (float)(hh + (TAP) / 3 - 1) + dy;                       \
        const float pxx = (float)(wx + (TAP) % 3 - 1) + dx;                      \
        const float y0f = floorf(py), x0f = floorf(pxx);                         \
        const float fy = py - y0f, fx = pxx - x0f;                               \
        const int y0 = (int)y0f, x0 = (int)x0f, y1 = y0 + 1, x1 = x0 + 1;        \
        float w00 = (1.f - fy) * (1.f - fx), w01 = (1.f - fy) * fx;              \
        float w10 = fy * (1.f - fx), w11 = fy * fx;                              \
        if (!((unsigned)y0 < 64u && (unsigned)x0 < 64u)) w00 = 0.f;              \
        if (!((unsigned)y0 < 64u && (unsigned)x1 < 64u)) w01 = 0.f;              \
        if (!((unsigned)y1 < 64u && (unsigned)x0 < 64u)) w10 = 0.f;              \
        if (!((unsigned)y1 < 64u && (unsigned)x1 < 64u)) w11 = 0.f;              \
        const int yc0 = min(max(y0, 0), 63), yc1 = min(max(y1, 0), 63);          \
        const int xc0 = min(max(x0, 0), 63), xc1 = min(max(x1, 0), 63);          \
        smi[(BASE) + t * 8 + 0] = (yc0 * 64 + xc0) * 256;                        \
        smi[(BASE) + t * 8 + 1] = (yc0 * 64 + xc1) * 256;                        \
        smi[(BASE) + t * 8 + 2] = (yc1 * 64 + xc0) * 256;                        \
        smi[(BASE) + t * 8 + 3] = (yc1 * 64 + xc1) * 256;                        \
        sm[(BASE) + t * 8 + 4] = w00; sm[(BASE) + t * 8 + 5] = w01;              \
        sm[(BASE) + t * 8 + 6] = w10; sm[(BASE) + t * 8 + 7] = w11;              \
    }

#define STAGE_B(CH, BUF) {                                                       \
        const float4* src = (const float4*)(g_wH + (size_t)(CH) * 4352);         \
        const uint32_t db = sb + (W_B + (BUF) * 4352) * 4;                       \
        _Pragma("unroll")                                                        \
        for (int i = 0; i < 4; i++)                                              \
            cp_async16(db + (uint32_t)(t + (i << 8)) * 16, src + t + (i << 8));  \
        if (t < 64) cp_async16(db + (uint32_t)(1024 + t) * 16, src + 1024 + t);  \
    }

// one pixel per phase: px = 2g + JJ; 4 fp16 channels at slot l8
#define GATHER_PX(JJ, CBASE, CB) {                                               \
        const int choff = (CB) + (l8 << 2);                                      \
        const int px = 2 * g + (JJ);                                             \
        const int* ci = smi + (CBASE) + px * 8;                                  \
        const float* cf = sm + (CBASE) + px * 8;                                 \
        wh[0] = __float2half2_rn(cf[4]);                                         \
        wh[1] = __float2half2_rn(cf[5]);                                         \
        wh[2] = __float2half2_rn(cf[6]);                                         \
        wh[3] = __float2half2_rn(cf[7]);                                         \
        ha[0] = *(const uint2*)(xb + ci[0] + choff);                             \
        ha[1] = *(const uint2*)(xb + ci[1] + choff);                             \
        ha[2] = *(const uint2*)(xb + ci[2] + choff);                             \
        ha[3] = *(const uint2*)(xb + ci[3] + choff);                             \
    }

#define COMBINE_PX(JJ, ABASE) {                                                  \
        const int px = 2 * g + (JJ);                                             \
        __half2 v01 = __hmul2(u2h(ha[0].x), wh[0]);                              \
        v01 = __hfma2(u2h(ha[1].x), wh[1], v01);                                 \
        v01 = __hfma2(u2h(ha[2].x), wh[2], v01);                                 \
        v01 = __hfma2(u2h(ha[3].x), wh[3], v01);                                 \
        __half2 v23 = __hmul2(u2h(ha[0].y), wh[0]);                              \
        v23 = __hfma2(u2h(ha[1].y), wh[1], v23);                                 \
        v23 = __hfma2(u2h(ha[2].y), wh[2], v23);                                 \
        v23 = __hfma2(u2h(ha[3].y), wh[3], v23);                                 \
        sm[(ABASE) + (2 * l8) * 69 + px]     = __uint_as_float(h2u(v01));        \
        sm[(ABASE) + (2 * l8 + 1) * 69 + px] = __uint_as_float(h2u(v23));        \
    }

#define MMA_KT(KT, ABASE, BBASE) {                                               \
        const uint32_t* Ah = (const uint32_t*)(sm + (ABASE));                    \
        const uint32_t* Bh = (const uint32_t*)(sm + (BBASE));                    \
        uint32_t af[2][4];                                                       \
        const int pa = (KT) * 8 + la;                                            \
        _Pragma("unroll")                                                        \
        for (int mt = 0; mt < 2; mt++) {                                         \
            const int base = pa * 69 + mg * 32 + mt * 16 + r;                    \
            af[mt][0] = Ah[base];          af[mt][1] = Ah[base + 8];             \
            af[mt][2] = Ah[base + 4 * 69]; af[mt][3] = Ah[base + 4 * 69 + 8];    \
        }                                                                        \
        _Pragma("unroll")                                                        \
        for (int nt = 0; nt < 8; nt++) {                                         \
            const int ob = (ng * 64 + nt * 8 + r) * 17 + (KT) * 8 + la;          \
            const uint32_t bh0 = Bh[ob], bh1 = Bh[ob + 4];                       \
            _Pragma("unroll")                                                    \
            for (int mt = 0; mt < 2; mt++) {                                     \
                mma16816(acc[mt][nt], af[mt][0], af[mt][1], af[mt][2], af[mt][3], bh0, bh1); \
            }                                                                    \
        }                                                                        \
    }

    uint2 ha[4];
    __half2 wh[4];

    // ---------------- prologue ----------------
    COORDS(0, W_COORD);
    __syncthreads();
    STAGE_B(0, 0);
    CP_COMMIT();
    GATHER_PX(0, W_COORD, 0);
    COMBINE_PX(0, W_A);
    GATHER_PX(1, W_COORD, 0);
    COMBINE_PX(1, W_A);
    CP_WAIT0();
    __syncthreads();

    // ---------------- main loop ----------------
#pragma unroll 1
    for (int k = 0; k < NCHUNK; ++k) {
        const int buf = k & 1, nbuf = buf ^ 1;
        const bool nx = (k + 1 < NCHUNK);
        const int abase = W_A + buf * 1104, bbase = W_B + buf * 4352;
        const int anext = W_A + nbuf * 1104;
        const int tapN = (k + 1) >> 3;
        const int cbase = W_COORD + (tapN & 1) * 512;
        const int cbch = ((k + 1) & 7) << 5;

        if (nx) STAGE_B(k + 1, nbuf);
        CP_COMMIT();

        if (nx) GATHER_PX(0, cbase, cbch);
        MMA_KT(0, abase, bbase);
        if (nx) COMBINE_PX(0, anext);

        if (nx) GATHER_PX(1, cbase, cbch);
        MMA_KT(1, abase, bbase);
        if (nx) COMBINE_PX(1, anext);

        if (((k + 2) & 7) == 0 && (k + 2) < NCHUNK) {
            const int t2 = (k + 2) >> 3;
            COORDS(t2, W_COORD + (t2 & 1) * 512);
        }
        CP_WAIT0();
        __syncthreads();
    }

    // ---------------- epilogue: relu + wcls dot, reduce over o ----------------
    {
        float s[2][2];
#pragma unroll
        for (int mt = 0; mt < 2; mt++) { s[mt][0] = 0.f; s[mt][1] = 0.f; }
#pragma unroll
        for (int nt = 0; nt < 8; nt++) {
            const int col = ng * 64 + nt * 8 + 2 * la;
            const float wc0 = __ldg(&wcls[col]), wc1 = __ldg(&wcls[col + 1]);
#pragma unroll
            for (int mt = 0; mt < 2; mt++) {
                s[mt][0] += wc0 * fmaxf(acc[mt][nt][0], 0.f) + wc1 * fmaxf(acc[mt][nt][1], 0.f);
                s[mt][1] += wc0 * fmaxf(acc[mt][nt][2], 0.f) + wc1 * fmaxf(acc[mt][nt][3], 0.f);
            }
        }
#pragma unroll
        for (int d = 1; d <= 2; d <<= 1)
#pragma unroll
            for (int mt = 0; mt < 2; mt++) {
                s[mt][0] += __shfl_xor_sync(0xFFFFFFFFu, s[mt][0], d);
                s[mt][1] += __shfl_xor_sync(0xFFFFFFFFu, s[mt][1], d);
            }
        __syncthreads();
        if (la == 0) {
#pragma unroll
            for (int mt = 0; mt < 2; mt++) {
                const int px = mg * 32 + mt * 16 + r;
                sm[W_RED + ng * 64 + px] = s[mt][0];
                sm[W_RED + ng * 64 + px + 8] = s[mt][1];
            }
        }
        __syncthreads();
        if (t < 64) {
            out[(size_t)n * HWP + px0 + t] =
                sm[W_RED + t] + sm[W_RED + 64 + t] +
                sm[W_RED + 128 + t] + sm[W_RED + 192 + t] + bcls[0];
        }
    }
}

// ---------------- launch ----------------
extern "C" void kernel_launch(void* const* d_in, const int* in_sizes, int n_in,
                              void* d_out, int out_size) {
    const float* x      = (const float*)d_in[0];
    const float* offset = (const float*)d_in[1];
    const float* w_def  = (const float*)d_in[2];
    const float* w_cls  = (const float*)d_in[3];
    const float* b_cls  = (const float*)d_in[4];
    float* out = (float*)d_out;

    dim3 g1(HWP / 32, CC / 64, NN), b1(32, 8);
    transpose_x_kernel<<<g1, b1>>>(x);
    wprep_kernel<<<(NCHUNK * 256 * 16 + 255) / 256, 256>>>(w_def);

    cudaFuncSetAttribute(deform_mma_kernel,
                         cudaFuncAttributeMaxDynamicSharedMemorySize, SMEM_BYTES);
    deform_mma_kernel<<<NN * 64, 256, SMEM_BYTES>>>(offset, w_cls, b_cls, out);
}

// round 11
// speedup vs baseline: 6.5058x; 1.2530x over previous
#include <cuda_runtime.h>
#include <cuda_fp16.h>
#include <cstdint>
#include <math.h>

#define NN 16
#define CC 256
#define OO 256
#define HWP 4096
#define NCHUNK 36          // 9 taps x 4 chunks of 64 channels

__device__ __half g_xT[(size_t)NN * HWP * CC];  // NHWC fp16 input
__device__ float g_wB[(size_t)NCHUNK * 9216];   // per chunk: B[256 o][36 words] (32 kpair + 4 pad)

// ---------------- helpers ----------------
__device__ __forceinline__ uint32_t smem_u32(const void* p) {
    uint32_t a;
    asm("{ .reg .u64 t; cvta.to.shared.u64 t, %1; cvt.u32.u64 %0, t; }" : "=r"(a) : "l"(p));
    return a;
}
__device__ __forceinline__ void cp_async16(uint32_t d, const void* s) {
    asm volatile("cp.async.ca.shared.global [%0], [%1], 16;" :: "r"(d), "l"(s));
}
#define CP_COMMIT() asm volatile("cp.async.commit_group;" ::: "memory")
#define CP_WAIT0()  asm volatile("cp.async.wait_group 0;" ::: "memory")

__device__ __forceinline__ __half2 u2h(uint32_t v) { return *(__half2*)&v; }
__device__ __forceinline__ uint32_t h2u(__half2 v) { return *(uint32_t*)&v; }

__device__ __forceinline__ void mma16816(float* c, uint32_t a0, uint32_t a1,
                                         uint32_t a2, uint32_t a3,
                                         uint32_t b0, uint32_t b1) {
    asm volatile(
        "mma.sync.aligned.m16n8k16.row.col.f32.f16.f16.f32 "
        "{%0,%1,%2,%3}, {%4,%5,%6,%7}, {%8,%9}, {%0,%1,%2,%3};"
        : "+f"(c[0]), "+f"(c[1]), "+f"(c[2]), "+f"(c[3])
        : "r"(a0), "r"(a1), "r"(a2), "r"(a3), "r"(b0), "r"(b1));
}

// ---------------- kernel 1: NCHW f32 -> NHWC fp16 ----------------
__global__ void transpose_x_kernel(const float* __restrict__ x) {
    __shared__ float tile[64][33];
    const int n = blockIdx.z, s0 = blockIdx.x * 32, c0 = blockIdx.y * 64;
    const int tx = threadIdx.x, ty = threadIdx.y;   // (32, 8)
    const float* xp = x + (size_t)n * CC * HWP;
#pragma unroll
    for (int j = 0; j < 8; j++)
        tile[ty + j * 8][tx] = xp[(size_t)(c0 + ty + j * 8) * HWP + s0 + tx];
    __syncthreads();
    __half* xt = g_xT + (size_t)n * HWP * CC;
#pragma unroll
    for (int j = 0; j < 4; j++) {
        const int s = ty + j * 8;
        __half2 hv = __floats2half2_rn(tile[2 * tx][s], tile[2 * tx + 1][s]);
        *(__half2*)(xt + (size_t)(s0 + s) * CC + c0 + 2 * tx) = hv;
    }
}

// ---------------- kernel 2: weights fp16, [chunk][o][36] (32 kpair + pad) ----------------
__global__ void wprep_kernel(const float* __restrict__ wdef) {
    int idx = blockIdx.x * blockDim.x + threadIdx.x;
    if (idx >= NCHUNK * 256 * 32) return;
    int p2 = idx & 31, o = (idx >> 5) & 255, chunk = idx >> 13;
    int tap = chunk >> 2, cg4 = chunk & 3;
    int c0 = cg4 * 64 + 2 * p2;
    float w0 = wdef[((size_t)o * CC + c0) * 9 + tap];
    float w1 = wdef[((size_t)o * CC + c0 + 1) * 9 + tap];
    __half2 hp = __halves2half2(__float2half_rn(w0), __float2half_rn(w1));
    g_wB[(size_t)chunk * 9216 + o * 36 + p2] = __uint_as_float(h2u(hp));
}

// ---------------- kernel 3: M=64 tiles, K=64 chunks, 2 CTAs/SM ----------------
// SMEM word offsets
#define W_COORD 0                 // 2 x [64 px][8]  (tap parity) = 1024
#define W_RED   1024              // 256
#define W_A     1280              // 2 x [64 px][36 words] = 4608 (chunk parity)
#define W_B     5888              // 2 x [256 o][36 words] = 18432
#define SMEM_WORDS 24320
#define SMEM_BYTES (SMEM_WORDS * 4)   // 97280

__global__ void __launch_bounds__(256, 2)
deform_mma_kernel(const float* __restrict__ off, const float* __restrict__ wcls,
                  const float* __restrict__ bcls, float* __restrict__ out) {
    extern __shared__ float sm[];
    int* smi = (int*)sm;
    const uint32_t sb = smem_u32(sm);
    const int t = threadIdx.x, lane = t & 31, w = t >> 5;
    const int mg = w >> 2, ng = w & 3;               // 2 m-groups x 4 n-groups
    const int n = blockIdx.x >> 6, pblk = blockIdx.x & 63;
    const int px0 = pblk * 64;
    const int pxt = t >> 2, cs = t & 3;              // gather: 1 px, 16 ch per thread
    const int la = lane & 3, r = lane >> 2;
    const __half* xb = g_xT + (size_t)n * HWP * CC;

    float acc[2][8][4];
#pragma unroll
    for (int a = 0; a < 2; a++)
#pragma unroll
        for (int b = 0; b < 8; b++)
#pragma unroll
            for (int c = 0; c < 4; c++) acc[a][b][c] = 0.f;

#define COORDS(TAP, BASE)                                                        \
    if (t < 64) {                                                                \
        const int gpix = px0 + t, hh = gpix >> 6, wx = gpix & 63;                \
        const float* op = off + (size_t)(n * HWP + gpix) * 18 + 2 * (TAP);       \
        const float dy = op[0], dx = op[1];                                      \
        const float py = (float)(hh + (TAP) / 3 - 1) + dy;                       \
        const float pxx = (float)(wx + (TAP) % 3 - 1) + dx;                      \
        const float y0f = floorf(py), x0f = floorf(pxx);                         \
        const float fy = py - y0f, fx = pxx - x0f;                               \
        const int y0 = (int)y0f, x0 = (int)x0f, y1 = y0 + 1, x1 = x0 + 1;        \
        float w00 = (1.f - fy) * (1.f - fx), w01 = (1.f - fy) * fx;              \
        float w10 = fy * (1.f - fx), w11 = fy * fx;                              \
        if (!((unsigned)y0 < 64u && (unsigned)x0 < 64u)) w00 = 0.f;              \
        if (!((unsigned)y0 < 64u && (unsigned)x1 < 64u)) w01 = 0.f;              \
        if (!((unsigned)y1 < 64u && (unsigned)x0 < 64u)) w10 = 0.f;              \
        if (!((unsigned)y1 < 64u && (unsigned)x1 < 64u)) w11 = 0.f;              \
        const int yc0 = min(max(y0, 0), 63), yc1 = min(max(y1, 0), 63);          \
        const int xc0 = min(max(x0, 0), 63), xc1 = min(max(x1, 0), 63);          \
        smi[(BASE) + t * 8 + 0] = (yc0 * 64 + xc0) * 256;                        \
        smi[(BASE) + t * 8 + 1] = (yc0 * 64 + xc1) * 256;                        \
        smi[(BASE) + t * 8 + 2] = (yc1 * 64 + xc0) * 256;                        \
        smi[(BASE) + t * 8 + 3] = (yc1 * 64 + xc1) * 256;                        \
        sm[(BASE) + t * 8 + 4] = w00; sm[(BASE) + t * 8 + 5] = w01;              \
        sm[(BASE) + t * 8 + 6] = w10; sm[(BASE) + t * 8 + 7] = w11;              \
    }

#define STAGE_B(CH, BUF) {                                                       \
        const float4* src = (const float4*)(g_wB + (size_t)(CH) * 9216);         \
        const uint32_t db = sb + (W_B + (BUF) * 9216) * 4;                       \
        _Pragma("unroll")                                                        \
        for (int i = 0; i < 9; i++)                                              \
            cp_async16(db + (uint32_t)(t + (i << 8)) * 16, src + t + (i << 8));  \
    }

// phase HF loads 8 channels (1 uint4 = 16B) per corner at ch = cs*16 + HF*8
#define GATHER_PHASE(HF, CBASE, CB) {                                            \
        const int choff = (CB) + cs * 16 + (HF) * 8;                             \
        const int* ci = smi + (CBASE) + pxt * 8;                                 \
        const float* cf = sm + (CBASE) + pxt * 8;                                \
        wh[0] = __float2half2_rn(cf[4]);                                         \
        wh[1] = __float2half2_rn(cf[5]);                                         \
        wh[2] = __float2half2_rn(cf[6]);                                         \
        wh[3] = __float2half2_rn(cf[7]);                                         \
        ga[0] = *(const uint4*)(xb + ci[0] + choff);                             \
        ga[1] = *(const uint4*)(xb + ci[1] + choff);                             \
        ga[2] = *(const uint4*)(xb + ci[2] + choff);                             \
        ga[3] = *(const uint4*)(xb + ci[3] + choff);                             \
    }

// combine -> A[px][36]: 4 contiguous words, one STS.128, conflict-free
#define COMBINE_PHASE(HF, ABASE) {                                               \
        __half2 v0 = __hmul2(u2h(ga[0].x), wh[0]);                               \
        v0 = __hfma2(u2h(ga[1].x), wh[1], v0);                                   \
        v0 = __hfma2(u2h(ga[2].x), wh[2], v0);                                   \
        v0 = __hfma2(u2h(ga[3].x), wh[3], v0);                                   \
        __half2 v1 = __hmul2(u2h(ga[0].y), wh[0]);                               \
        v1 = __hfma2(u2h(ga[1].y), wh[1], v1);                                   \
        v1 = __hfma2(u2h(ga[2].y), wh[2], v1);                                   \
        v1 = __hfma2(u2h(ga[3].y), wh[3], v1);                                   \
        __half2 v2 = __hmul2(u2h(ga[0].z), wh[0]);                               \
        v2 = __hfma2(u2h(ga[1].z), wh[1], v2);                                   \
        v2 = __hfma2(u2h(ga[2].z), wh[2], v2);                                   \
        v2 = __hfma2(u2h(ga[3].z), wh[3], v2);                                   \
        __half2 v3 = __hmul2(u2h(ga[0].w), wh[0]);                               \
        v3 = __hfma2(u2h(ga[1].w), wh[1], v3);                                   \
        v3 = __hfma2(u2h(ga[2].w), wh[2], v3);                                   \
        v3 = __hfma2(u2h(ga[3].w), wh[3], v3);                                   \
        float4 pk;                                                               \
        pk.x = __uint_as_float(h2u(v0)); pk.y = __uint_as_float(h2u(v1));        \
        pk.z = __uint_as_float(h2u(v2)); pk.w = __uint_as_float(h2u(v3));        \
        *(float4*)(sm + (ABASE) + pxt * 36 + cs * 8 + (HF) * 4) = pk;            \
    }

#define MMA_KT(KT, ABASE, BBASE) {                                               \
        const uint32_t* Ah = (const uint32_t*)(sm + (ABASE));                    \
        const uint32_t* Bh = (const uint32_t*)(sm + (BBASE));                    \
        uint32_t af[2][4];                                                       \
        _Pragma("unroll")                                                        \
        for (int mt = 0; mt < 2; mt++) {                                         \
            const int base = (mg * 32 + mt * 16 + r) * 36 + (KT) * 8 + la;       \
            af[mt][0] = Ah[base];       af[mt][1] = Ah[base + 288];              \
            af[mt][2] = Ah[base + 4];   af[mt][3] = Ah[base + 292];              \
        }                                                                        \
        _Pragma("unroll")                                                        \
        for (int nt = 0; nt < 8; nt++) {                                         \
            const int ob = (ng * 64 + nt * 8 + r) * 36 + (KT) * 8 + la;          \
            const uint32_t bh0 = Bh[ob], bh1 = Bh[ob + 4];                       \
            _Pragma("unroll")                                                    \
            for (int mt = 0; mt < 2; mt++) {                                     \
                mma16816(acc[mt][nt], af[mt][0], af[mt][1], af[mt][2], af[mt][3], bh0, bh1); \
            }                                                                    \
        }                                                                        \
    }

    uint4 ga[4];
    __half2 wh[4];

    // ---------------- prologue ----------------
    COORDS(0, W_COORD);
    __syncthreads();
    STAGE_B(0, 0);
    CP_COMMIT();
    GATHER_PHASE(0, W_COORD, 0);
    COMBINE_PHASE(0, W_A);
    GATHER_PHASE(1, W_COORD, 0);
    COMBINE_PHASE(1, W_A);
    CP_WAIT0();
    __syncthreads();

    // ---------------- main loop ----------------
#pragma unroll 1
    for (int k = 0; k < NCHUNK; ++k) {
        const int buf = k & 1, nbuf = buf ^ 1;
        const bool nx = (k + 1 < NCHUNK);
        const int abase = W_A + buf * 2304, bbase = W_B + buf * 9216;
        const int anext = W_A + nbuf * 2304;
        const int tapN = (k + 1) >> 2;
        const int cbase = W_COORD + (tapN & 1) * 512;
        const int cbch = ((k + 1) & 3) << 6;

        if (nx) STAGE_B(k + 1, nbuf);
        CP_COMMIT();

        if (nx) GATHER_PHASE(0, cbase, cbch);
        MMA_KT(0, abase, bbase);
        MMA_KT(1, abase, bbase);
        if (nx) COMBINE_PHASE(0, anext);

        if (nx) GATHER_PHASE(1, cbase, cbch);
        MMA_KT(2, abase, bbase);
        MMA_KT(3, abase, bbase);
        if (nx) COMBINE_PHASE(1, anext);

        if (((k + 2) & 3) == 0 && (k + 2) < NCHUNK) {
            const int t2 = (k + 2) >> 2;
            COORDS(t2, W_COORD + (t2 & 1) * 512);
        }
        CP_WAIT0();
        __syncthreads();
    }

    // ---------------- epilogue: relu + wcls dot, reduce over o ----------------
    {
        float s[2][2];
#pragma unroll
        for (int mt = 0; mt < 2; mt++) { s[mt][0] = 0.f; s[mt][1] = 0.f; }
#pragma unroll
        for (int nt = 0; nt < 8; nt++) {
            const int col = ng * 64 + nt * 8 + 2 * la;
            const float wc0 = __ldg(&wcls[col]), wc1 = __ldg(&wcls[col + 1]);
#pragma unroll
            for (int mt = 0; mt < 2; mt++) {
                s[mt][0] += wc0 * fmaxf(acc[mt][nt][0], 0.f) + wc1 * fmaxf(acc[mt][nt][1], 0.f);
                s[mt][1] += wc0 * fmaxf(acc[mt][nt][2], 0.f) + wc1 * fmaxf(acc[mt][nt][3], 0.f);
            }
        }
#pragma unroll
        for (int d = 1; d <= 2; d <<= 1)
#pragma unroll
            for (int mt = 0; mt < 2; mt++) {
                s[mt][0] += __shfl_xor_sync(0xFFFFFFFFu, s[mt][0], d);
                s[mt][1] += __shfl_xor_sync(0xFFFFFFFFu, s[mt][1], d);
            }
        __syncthreads();
        if (la == 0) {
#pragma unroll
            for (int mt = 0; mt < 2; mt++) {
                const int px = mg * 32 + mt * 16 + r;
                sm[W_RED + ng * 64 + px] = s[mt][0];
                sm[W_RED + ng * 64 + px + 8] = s[mt][1];
            }
        }
        __syncthreads();
        if (t < 64) {
            out[(size_t)n * HWP + px0 + t] =
                sm[W_RED + t] + sm[W_RED + 64 + t] +
                sm[W_RED + 128 + t] + sm[W_RED + 192 + t] + bcls[0];
        }
    }
}

// ---------------- launch ----------------
extern "C" void kernel_launch(void* const* d_in, const int* in_sizes, int n_in,
                              void* d_out, int out_size) {
    const float* x      = (const float*)d_in[0];
    const float* offset = (const float*)d_in[1];
    const float* w_def  = (const float*)d_in[2];
    const float* w_cls  = (const float*)d_in[3];
    const float* b_cls  = (const float*)d_in[4];
    float* out = (float*)d_out;

    dim3 g1(HWP / 32, CC / 64, NN), b1(32, 8);
    transpose_x_kernel<<<g1, b1>>>(x);
    wprep_kernel<<<(NCHUNK * 256 * 32 + 255) / 256, 256>>>(w_def);

    cudaFuncSetAttribute(deform_mma_kernel,
                         cudaFuncAttributeMaxDynamicSharedMemorySize, SMEM_BYTES);
    deform_mma_kernel<<<NN * 64, 256, SMEM_BYTES>>>(offset, w_cls, b_cls, out);
}